// round 9
// baseline (speedup 1.0000x reference)
#include <cuda_runtime.h>
#include <cuda_pipeline.h>

// ---------------------------------------------------------------------------
// SNN ResNet forward, 8 timesteps, B=32. fp32 smem-tiled convs with cp.async
// double buffering; deep layers split each chunk's ci-compute across KS
// thread-slices (shared staging buffers, smem reduce). Fused LIF / masks /
// residuals / 1x1-s2 shortcuts / avgpool. Layer-0 conv hoisted.
// ---------------------------------------------------------------------------

#define B 32
#define TSTEPS 8

#define OFF_M0  0u
#define OFF_M1  2097152u
#define OFF_M2  4194304u
#define OFF_M3  6291456u
#define OFF_M4  6815744u
#define OFF_M5  7340032u
#define OFF_M6  7602176u
#define OFF_M7  7864320u
#define OFF_M8  7995392u
#define OFF_M9  8126464u
#define OFF_M10 8192000u
#define MEM_TOTAL 8257536u

__device__ float g_mem[MEM_TOTAL];
__device__ float g_A[2097152];
__device__ float g_B[2097152];
__device__ float g_C[2097152];
__device__ float g_D[2097152];   // precomputed conv(x, w_pre0)

__global__ void zero_kernel(float* __restrict__ p, int n) {
    int i = blockIdx.x * blockDim.x + threadIdx.x;
    if (i < n) p[i] = 0.0f;
}

// elementwise LIF for layer 0, float4-vectorized (delta precomputed)
__global__ __launch_bounds__(256)
void lif0_kernel(const float4* __restrict__ delta, float4* __restrict__ mem,
                 const float4* __restrict__ mask, float4* __restrict__ out,
                 const float* __restrict__ thr_a, const float* __restrict__ leak_a) {
    int i = blockIdx.x * blockDim.x + threadIdx.x;
    float thr = __ldg(thr_a), leak = __ldg(leak_a);
    float4 d = __ldg(delta + i);
    float4 mm = mem[i];
    float4 mk = __ldg(mask + i);
    float4 o, nm;
    { float m = fmaf(leak, mm.x, d.x); float s = (m / thr > 1.0f) ? 1.0f : 0.0f;
      nm.x = m - thr * s; o.x = s * mk.x; }
    { float m = fmaf(leak, mm.y, d.y); float s = (m / thr > 1.0f) ? 1.0f : 0.0f;
      nm.y = m - thr * s; o.y = s * mk.y; }
    { float m = fmaf(leak, mm.z, d.z); float s = (m / thr > 1.0f) ? 1.0f : 0.0f;
      nm.z = m - thr * s; o.z = s * mk.z; }
    { float m = fmaf(leak, mm.w, d.w); float s = (m / thr > 1.0f) ? 1.0f : 0.0f;
      nm.w = m - thr * s; o.w = s * mk.w; }
    mem[i] = nm;
    out[i] = o;
}

// ---------------------------------------------------------------------------
// Fused 3x3 conv (pad=1) + (residual | fused 1x1-s2 shortcut) + LIF + mask
// (+ optional fused 2x2 avgpool). All NT threads cooperatively stage each
// chunk (double-buffered cp.async); KS slices split each chunk's ci range.
// mem == nullptr  =>  raw conv output (no LIF), used for hoisted layer 0.
// ---------------------------------------------------------------------------
template<int H, int CI, int CO, int STRIDE, int CIC, int TH, int TW,
         int CO_T, int B_T, int NT, int SC_CI, int POOL, int KS>
__global__ __launch_bounds__(NT)
void conv_fused(const float* __restrict__ in, const float* __restrict__ wgt,
                const float* __restrict__ res, const float* __restrict__ mask,
                const float* __restrict__ sc_in, const float* __restrict__ sc_w,
                float* __restrict__ mem, float* __restrict__ out,
                const float* __restrict__ thr_a, const float* __restrict__ leak_a,
                int lidx) {
    constexpr int HO = H / STRIDE;
    constexpr int WO = HO;
    constexpr int TILESH = HO / TH;
    constexpr int TILESW = WO / TW;
    constexpr int TILES = TILESH * TILESW;
    constexpr int SNT = NT / KS;
    static_assert(TILES * CO_T * B_T == SNT, "slice thread count mismatch");
    static_assert(CIC % KS == 0, "KS must divide CIC");
    static_assert((TW * STRIDE) % 4 == 0 || TILESW == 1, "LDS.128 alignment");
    constexpr int RH = (TH - 1) * STRIDE + 3;
    constexpr int RW = (TW - 1) * STRIDE + 3;
    constexpr int NV4 = (RW + 3) / 4;
    constexpr int SWMIN = (H + 2 > NV4 * 4) ? (H + 2) : (NV4 * 4);
    constexpr int SW = ((SWMIN + 3) / 4) * 4;   // smem row stride (interior col 1)
    constexpr int HI2 = H + 2;
    constexpr int IN_CH = HI2 * SW;
    constexpr int IN_IMG = CIC * IN_CH;
    constexpr int IN_TOT = B_T * IN_IMG;
    constexpr int W_TOT = CO_T * CIC * 9;
    constexpr int CHUNKS = CI / CIC;
    constexpr int CIS = CIC / KS;               // ci per slice per chunk
    constexpr int THW = TH * TW;
    constexpr int RED_SZ = (KS > 1) ? (KS - 1) * SNT * THW : 1;

    __shared__ alignas(16) float s_in[2][IN_TOT];
    __shared__ alignas(16) float s_w[2][W_TOT];
    __shared__ float s_red[RED_SZ];

    const int tid = threadIdx.x;
    const int stid = tid % SNT;
    const int ks = tid / SNT;
    const int tile = stid % TILES;
    const int co_l = (stid / TILES) % CO_T;
    const int b_l  = stid / (TILES * CO_T);
    const int co_g = blockIdx.x % (CO / CO_T);
    const int b_g  = blockIdx.x / (CO / CO_T);
    const int b  = b_g * B_T + b_l;
    const int co = co_g * CO_T + co_l;
    const int oh0 = (tile / TILESW) * TH;
    const int ow0 = (tile % TILESW) * TW;

    // zero both input buffers once: halo / padding stays zero for all chunks
    {
        const float4 z4 = make_float4(0.f, 0.f, 0.f, 0.f);
        for (int i = tid * 4; i < IN_TOT; i += NT * 4) {
            *reinterpret_cast<float4*>(&s_in[0][i]) = z4;
            *reinterpret_cast<float4*>(&s_in[1][i]) = z4;
        }
    }
    __syncthreads();

    // stage chunk cc into buffer buf — all NT threads cooperate
    auto stage = [&](int buf, int cc) {
        constexpr int NE = B_T * CIC * H * H;
        for (int e = tid; e < NE; e += NT) {
            const int wq = e % H;
            int r = e / H;
            const int h = r % H; r /= H;
            const int ci = r % CIC;
            const int bl = r / CIC;
            const float* src = in + (((size_t)(b_g * B_T + bl) * CI + cc * CIC + ci) * H + h) * H + wq;
            __pipeline_memcpy_async(&s_in[buf][bl * IN_IMG + ci * IN_CH + (h + 1) * SW + 1 + wq],
                                    src, 4);
        }
        for (int e = tid; e < W_TOT; e += NT) {
            const int rem = e % (CIC * 9);
            const int col = e / (CIC * 9);
            const float* src = wgt + ((size_t)(co_g * CO_T + col) * CI + cc * CIC) * 9 + rem;
            __pipeline_memcpy_async(&s_w[buf][col * CIC * 9 + rem], src, 4);
        }
    };

    float acc[THW];
#pragma unroll
    for (int i = 0; i < THW; ++i) acc[i] = 0.0f;

    stage(0, 0);
    __pipeline_commit();

    for (int cc = 0; cc < CHUNKS; ++cc) {
        const int cur = cc & 1;
        if (cc + 1 < CHUNKS) {
            stage(cur ^ 1, cc + 1);
            __pipeline_commit();
            __pipeline_wait_prior(1);
        } else {
            __pipeline_wait_prior(0);
        }
        __syncthreads();

        const float* sin_b = &s_in[cur][b_l * IN_IMG + (oh0 * STRIDE) * SW + ow0 * STRIDE];
        const float* sw_c  = &s_w[cur][co_l * CIC * 9];
        const int ci0 = ks * CIS;
        for (int ci = ci0; ci < ci0 + CIS; ++ci) {
            float w9[9];
#pragma unroll
            for (int k = 0; k < 9; ++k) w9[k] = sw_c[ci * 9 + k];
            const float* sp = sin_b + ci * IN_CH;
#pragma unroll
            for (int r = 0; r < RH; ++r) {
                float v[NV4 * 4];
#pragma unroll
                for (int q = 0; q < NV4; ++q)
                    *reinterpret_cast<float4*>(v + 4 * q) =
                        *reinterpret_cast<const float4*>(sp + r * SW + 4 * q);
#pragma unroll
                for (int kh = 0; kh < 3; ++kh) {
                    if (r - kh >= 0 && (r - kh) % STRIDE == 0 && (r - kh) / STRIDE < TH) {
                        const int ii = (r - kh) / STRIDE;
#pragma unroll
                        for (int kw = 0; kw < 3; ++kw)
#pragma unroll
                            for (int j = 0; j < TW; ++j)
                                acc[ii * TW + j] = fmaf(w9[kh * 3 + kw],
                                                        v[j * STRIDE + kw],
                                                        acc[ii * TW + j]);
                    }
                }
            }
        }
        __syncthreads();
    }

    // K-split reduction: slices > 0 publish, slice 0 accumulates
    if (KS > 1) {
        if (ks > 0) {
#pragma unroll
            for (int i = 0; i < THW; ++i)
                s_red[(ks - 1) * SNT * THW + stid * THW + i] = acc[i];
        }
        __syncthreads();
        if (ks != 0) return;
#pragma unroll
        for (int k = 1; k < KS; ++k)
#pragma unroll
            for (int i = 0; i < THW; ++i)
                acc[i] += s_red[(k - 1) * SNT * THW + stid * THW + i];
    }

    // fused 1x1-s2 shortcut conv
    float rsum[THW];
    if (SC_CI > 0) {
#pragma unroll
        for (int i = 0; i < THW; ++i) rsum[i] = 0.0f;
        const float* wp = sc_w + (size_t)co * SC_CI;
        for (int ci = 0; ci < SC_CI; ++ci) {
            float wv = __ldg(wp + ci);
            const float* ip = sc_in + ((size_t)b * SC_CI + ci) * (4 * HO * WO);
#pragma unroll
            for (int i = 0; i < TH; ++i)
#pragma unroll
                for (int j = 0; j < TW; ++j)
                    rsum[i * TW + j] = fmaf(wv,
                        __ldg(ip + (2 * (oh0 + i)) * (2 * WO) + 2 * (ow0 + j)),
                        rsum[i * TW + j]);
        }
    }

    const float thr  = __ldg(thr_a + lidx);
    const float leak = __ldg(leak_a + lidx);

    float s_tile[THW];
#pragma unroll
    for (int i = 0; i < TH; ++i) {
#pragma unroll
        for (int j = 0; j < TW; ++j) {
            size_t oi = (((size_t)b * CO + co) * HO + oh0 + i) * WO + ow0 + j;
            float d = acc[i * TW + j];
            if (SC_CI > 0) d += rsum[i * TW + j];
            else if (res) d += __ldg(res + oi);
            if (mem == nullptr) { out[oi] = d; continue; }
            float m = fmaf(leak, mem[oi], d);
            float mth = m / thr - 1.0f;
            float s = (mth > 0.0f) ? 1.0f : 0.0f;
            mem[oi] = m - thr * s;
            if (POOL) s_tile[i * TW + j] = s;
            else out[oi] = mask ? s * __ldg(mask + oi) : s;
        }
    }
    if (POOL && mem != nullptr) {
        constexpr int HOP = HO / 2, WOP = WO / 2;
#pragma unroll
        for (int i2 = 0; i2 < TH / 2; ++i2)
#pragma unroll
            for (int j2 = 0; j2 < TW / 2; ++j2) {
                float sum = s_tile[(2 * i2) * TW + 2 * j2] +
                            s_tile[(2 * i2) * TW + 2 * j2 + 1] +
                            s_tile[(2 * i2 + 1) * TW + 2 * j2] +
                            s_tile[(2 * i2 + 1) * TW + 2 * j2 + 1];
                out[(((size_t)b * CO + co) * HOP + (oh0 >> 1) + i2) * WOP +
                    (ow0 >> 1) + j2] = 0.25f * sum;
            }
    }
}

// FC accumulate: out[b,j] += sum_k in[b,k] * wfc[j,k].  One warp per output.
__global__ __launch_bounds__(256)
void fc_acc(const float* __restrict__ in, const float* __restrict__ wfc,
            float* __restrict__ out) {
    int gw = (blockIdx.x * blockDim.x + threadIdx.x) >> 5;
    int lane = threadIdx.x & 31;
    if (gw >= B * 10) return;
    int b = gw / 10, j = gw % 10;
    const float* x = in + (size_t)b * 2048;
    const float* w = wfc + (size_t)j * 2048;
    float s = 0.f;
    for (int k = lane; k < 2048; k += 32) s = fmaf(x[k], w[k], s);
#pragma unroll
    for (int o = 16; o; o >>= 1) s += __shfl_down_sync(0xffffffffu, s, o);
    if (lane == 0) out[b * 10 + j] += s;
}

// -------------------------- host-side orchestration ------------------------

extern "C" void kernel_launch(void* const* d_in, const int* in_sizes, int n_in,
                              void* d_out, int out_size) {
    const float* x      = (const float*)d_in[0];
    const float* w_pre0 = (const float*)d_in[1];
    const float* w_pre1 = (const float*)d_in[2];
    const float* w_pre2 = (const float*)d_in[3];
    const float* w1a    = (const float*)d_in[4];
    const float* w1b    = (const float*)d_in[5];
    const float* w2a    = (const float*)d_in[6];
    const float* w2b    = (const float*)d_in[7];
    const float* w2i    = (const float*)d_in[8];
    const float* w3a    = (const float*)d_in[9];
    const float* w3b    = (const float*)d_in[10];
    const float* w3i    = (const float*)d_in[11];
    const float* w4a    = (const float*)d_in[12];
    const float* w4b    = (const float*)d_in[13];
    const float* w4i    = (const float*)d_in[14];
    const float* w_fc   = (const float*)d_in[15];
    const float* thr    = (const float*)d_in[16];
    const float* leak   = (const float*)d_in[17];
    const float* mask2  = (const float*)d_in[18];
    const float* mask5  = (const float*)d_in[19];
    const float* mask9  = (const float*)d_in[20];
    const float* mask11 = (const float*)d_in[21];
    const float* mask13 = (const float*)d_in[22];
    const float* mask15 = (const float*)d_in[23];

    float *pm, *pA, *pB, *pC, *pD;
    cudaGetSymbolAddress((void**)&pm, g_mem);
    cudaGetSymbolAddress((void**)&pA, g_A);
    cudaGetSymbolAddress((void**)&pB, g_B);
    cudaGetSymbolAddress((void**)&pC, g_C);
    cudaGetSymbolAddress((void**)&pD, g_D);

    float* m0  = pm + OFF_M0;
    float* m1  = pm + OFF_M1;
    float* m2  = pm + OFF_M2;
    float* m3  = pm + OFF_M3;
    float* m4  = pm + OFF_M4;
    float* m5  = pm + OFF_M5;
    float* m6  = pm + OFF_M6;
    float* m7  = pm + OFF_M7;
    float* m8  = pm + OFF_M8;
    float* m9  = pm + OFF_M9;
    float* m10 = pm + OFF_M10;

    zero_kernel<<<(MEM_TOTAL + 255) / 256, 256>>>(pm, (int)MEM_TOTAL);
    zero_kernel<<<2, 256>>>((float*)d_out, out_size);

    // hoisted: delta0 = conv(x, w_pre0), constant across timesteps
    conv_fused<32, 3, 64, 1, 3, 4, 4, 4, 1, 256, 0, 0, 1><<<512, 256>>>(
        x, w_pre0, nullptr, nullptr, nullptr, nullptr, nullptr, pD, thr, leak, 0);

    for (int t = 0; t < TSTEPS; ++t) {
        // layer 0: elementwise LIF on precomputed delta (float4)
        lif0_kernel<<<2048, 256>>>((const float4*)pD, (float4*)m0,
                                   (const float4*)mask2, (float4*)pA, thr + 0, leak + 0);

        // pre-process convs (32x32, 64ch); pre2 fuses the 2x2 avgpool
        conv_fused<32, 64, 64, 1, 4, 4, 4, 4, 1, 256, 0, 0, 1><<<512, 256>>>(
            pA, w_pre1, nullptr, mask5, nullptr, nullptr, m1, pB, thr, leak, 1);
        conv_fused<32, 64, 64, 1, 4, 4, 4, 4, 1, 256, 0, 1, 1><<<512, 256>>>(
            pB, w_pre2, nullptr, nullptr, nullptr, nullptr, m2, pC, thr, leak, 2);

        // layer1 (identity shortcut), 16x16x64: KS=2, 256 blocks
        conv_fused<16, 64, 64, 1, 8, 4, 4, 8, 1, 256, 0, 0, 2><<<256, 256>>>(
            pC, w1a, nullptr, mask9, nullptr, nullptr, m3, pA, thr, leak, 3);
        conv_fused<16, 64, 64, 1, 8, 4, 4, 8, 1, 256, 0, 0, 2><<<256, 256>>>(
            pA, w1b, pC, nullptr, nullptr, nullptr, m4, pB, thr, leak, 4);

        // layer2: 16x16x64 -> 8x8x128 (fused 1x1-s2 shortcut in conv-b)
        conv_fused<16, 64, 128, 2, 4, 2, 4, 16, 1, 256, 0, 0, 2><<<256, 256>>>(
            pB, w2a, nullptr, mask11, nullptr, nullptr, m5, pC, thr, leak, 5);
        conv_fused<8, 128, 128, 1, 8, 4, 4, 16, 2, 256, 64, 0, 2><<<128, 256>>>(
            pC, w2b, nullptr, nullptr, pB, w2i, m6, pA, thr, leak, 6);

        // layer3: 8x8x128 -> 4x4x256
        conv_fused<8, 128, 256, 2, 8, 2, 2, 16, 2, 256, 0, 0, 2><<<256, 256>>>(
            pA, w3a, nullptr, mask13, nullptr, nullptr, m7, pB, thr, leak, 7);
        conv_fused<4, 256, 256, 1, 8, 2, 4, 32, 2, 256, 128, 0, 2><<<128, 256>>>(
            pB, w3b, nullptr, nullptr, pA, w3i, m8, pC, thr, leak, 8);

        // layer4: 4x4x256 -> 2x2x512
        conv_fused<4, 256, 512, 2, 8, 2, 2, 32, 4, 256, 0, 0, 2><<<128, 256>>>(
            pC, w4a, nullptr, mask15, nullptr, nullptr, m9, pB, thr, leak, 9);
        conv_fused<2, 512, 512, 1, 16, 2, 2, 32, 4, 256, 256, 0, 2><<<128, 256>>>(
            pB, w4b, nullptr, nullptr, pC, w4i, m10, pA, thr, leak, 10);

        // classifier accumulation
        fc_acc<<<40, 256>>>(pA, w_fc, (float*)d_out);
    }
}

// round 10
// speedup vs baseline: 1.0045x; 1.0045x over previous
#include <cuda_runtime.h>
#include <cuda_pipeline.h>

// ---------------------------------------------------------------------------
// SNN ResNet forward, 8 timesteps, B=32. fp32 smem-tiled convs with cp.async
// double buffering; deep layers add warps via KS=2 ci-split per chunk with
// IDENTICAL grids/staging to the best (R7) config. Fused LIF / masks /
// residuals / 1x1-s2 shortcuts / avgpool. Layer-0 conv hoisted.
// ---------------------------------------------------------------------------

#define B 32
#define TSTEPS 8

#define OFF_M0  0u
#define OFF_M1  2097152u
#define OFF_M2  4194304u
#define OFF_M3  6291456u
#define OFF_M4  6815744u
#define OFF_M5  7340032u
#define OFF_M6  7602176u
#define OFF_M7  7864320u
#define OFF_M8  7995392u
#define OFF_M9  8126464u
#define OFF_M10 8192000u
#define MEM_TOTAL 8257536u

__device__ float g_mem[MEM_TOTAL];
__device__ float g_A[2097152];
__device__ float g_B[2097152];
__device__ float g_C[2097152];
__device__ float g_D[2097152];   // precomputed conv(x, w_pre0)

__global__ void zero_kernel(float* __restrict__ p, int n) {
    int i = blockIdx.x * blockDim.x + threadIdx.x;
    if (i < n) p[i] = 0.0f;
}

// elementwise LIF for layer 0, float4-vectorized (delta precomputed)
__global__ __launch_bounds__(256)
void lif0_kernel(const float4* __restrict__ delta, float4* __restrict__ mem,
                 const float4* __restrict__ mask, float4* __restrict__ out,
                 const float* __restrict__ thr_a, const float* __restrict__ leak_a) {
    int i = blockIdx.x * blockDim.x + threadIdx.x;
    float thr = __ldg(thr_a), leak = __ldg(leak_a);
    float4 d = __ldg(delta + i);
    float4 mm = mem[i];
    float4 mk = __ldg(mask + i);
    float4 o, nm;
    { float m = fmaf(leak, mm.x, d.x); float s = (m / thr > 1.0f) ? 1.0f : 0.0f;
      nm.x = m - thr * s; o.x = s * mk.x; }
    { float m = fmaf(leak, mm.y, d.y); float s = (m / thr > 1.0f) ? 1.0f : 0.0f;
      nm.y = m - thr * s; o.y = s * mk.y; }
    { float m = fmaf(leak, mm.z, d.z); float s = (m / thr > 1.0f) ? 1.0f : 0.0f;
      nm.z = m - thr * s; o.z = s * mk.z; }
    { float m = fmaf(leak, mm.w, d.w); float s = (m / thr > 1.0f) ? 1.0f : 0.0f;
      nm.w = m - thr * s; o.w = s * mk.w; }
    mem[i] = nm;
    out[i] = o;
}

// ---------------------------------------------------------------------------
// Fused 3x3 conv (pad=1) + (residual | fused 1x1-s2 shortcut) + LIF + mask
// (+ optional fused 2x2 avgpool). All NT threads stage each chunk
// (double-buffered cp.async); KS slices split each chunk's ci range.
// The K-split reduction scratch OVERLAYS the staging buffers (dead by then).
// mem == nullptr  =>  raw conv output (no LIF), used for hoisted layer 0.
// ---------------------------------------------------------------------------
template<int H, int CI, int CO, int STRIDE, int CIC, int TH, int TW,
         int CO_T, int B_T, int NT, int SC_CI, int POOL, int KS>
__global__ __launch_bounds__(NT)
void conv_fused(const float* __restrict__ in, const float* __restrict__ wgt,
                const float* __restrict__ res, const float* __restrict__ mask,
                const float* __restrict__ sc_in, const float* __restrict__ sc_w,
                float* __restrict__ mem, float* __restrict__ out,
                const float* __restrict__ thr_a, const float* __restrict__ leak_a,
                int lidx) {
    constexpr int HO = H / STRIDE;
    constexpr int WO = HO;
    constexpr int TILESH = HO / TH;
    constexpr int TILESW = WO / TW;
    constexpr int TILES = TILESH * TILESW;
    constexpr int SNT = NT / KS;
    static_assert(TILES * CO_T * B_T == SNT, "slice thread count mismatch");
    static_assert(CIC % KS == 0, "KS must divide CIC");
    static_assert((TW * STRIDE) % 4 == 0 || TILESW == 1, "LDS.128 alignment");
    constexpr int RH = (TH - 1) * STRIDE + 3;
    constexpr int RW = (TW - 1) * STRIDE + 3;
    constexpr int NV4 = (RW + 3) / 4;
    constexpr int SWMIN = (H + 2 > NV4 * 4) ? (H + 2) : (NV4 * 4);
    constexpr int SW = ((SWMIN + 3) / 4) * 4;   // smem row stride (interior col 1)
    constexpr int HI2 = H + 2;
    constexpr int IN_CH = HI2 * SW;
    constexpr int IN_IMG = CIC * IN_CH;
    constexpr int IN_TOT = B_T * IN_IMG;
    constexpr int W_TOT = CO_T * CIC * 9;
    constexpr int CHUNKS = CI / CIC;
    constexpr int CIS = CIC / KS;               // ci per slice per chunk
    constexpr int THW = TH * TW;
    constexpr int RED_SZ = (KS > 1) ? (KS - 1) * SNT * THW : 0;
    static_assert(RED_SZ <= 2 * IN_TOT, "reduction scratch must fit in staging overlay");

    __shared__ alignas(16) float s_in[2][IN_TOT];
    __shared__ alignas(16) float s_w[2][W_TOT];
    float* s_red = &s_in[0][0];   // overlay: valid only after final chunk barrier

    const int tid = threadIdx.x;
    const int stid = tid % SNT;
    const int ks = tid / SNT;
    const int tile = stid % TILES;
    const int co_l = (stid / TILES) % CO_T;
    const int b_l  = stid / (TILES * CO_T);
    const int co_g = blockIdx.x % (CO / CO_T);
    const int b_g  = blockIdx.x / (CO / CO_T);
    const int b  = b_g * B_T + b_l;
    const int co = co_g * CO_T + co_l;
    const int oh0 = (tile / TILESW) * TH;
    const int ow0 = (tile % TILESW) * TW;

    // zero both input buffers once: halo / padding stays zero for all chunks
    {
        const float4 z4 = make_float4(0.f, 0.f, 0.f, 0.f);
        for (int i = tid * 4; i < IN_TOT; i += NT * 4) {
            *reinterpret_cast<float4*>(&s_in[0][i]) = z4;
            *reinterpret_cast<float4*>(&s_in[1][i]) = z4;
        }
    }
    __syncthreads();

    // stage chunk cc into buffer buf — all NT threads cooperate
    auto stage = [&](int buf, int cc) {
        constexpr int NE = B_T * CIC * H * H;
        for (int e = tid; e < NE; e += NT) {
            const int wq = e % H;
            int r = e / H;
            const int h = r % H; r /= H;
            const int ci = r % CIC;
            const int bl = r / CIC;
            const float* src = in + (((size_t)(b_g * B_T + bl) * CI + cc * CIC + ci) * H + h) * H + wq;
            __pipeline_memcpy_async(&s_in[buf][bl * IN_IMG + ci * IN_CH + (h + 1) * SW + 1 + wq],
                                    src, 4);
        }
        for (int e = tid; e < W_TOT; e += NT) {
            const int rem = e % (CIC * 9);
            const int col = e / (CIC * 9);
            const float* src = wgt + ((size_t)(co_g * CO_T + col) * CI + cc * CIC) * 9 + rem;
            __pipeline_memcpy_async(&s_w[buf][col * CIC * 9 + rem], src, 4);
        }
    };

    float acc[THW];
#pragma unroll
    for (int i = 0; i < THW; ++i) acc[i] = 0.0f;

    stage(0, 0);
    __pipeline_commit();

    for (int cc = 0; cc < CHUNKS; ++cc) {
        const int cur = cc & 1;
        if (cc + 1 < CHUNKS) {
            stage(cur ^ 1, cc + 1);
            __pipeline_commit();
            __pipeline_wait_prior(1);
        } else {
            __pipeline_wait_prior(0);
        }
        __syncthreads();

        const float* sin_b = &s_in[cur][b_l * IN_IMG + (oh0 * STRIDE) * SW + ow0 * STRIDE];
        const float* sw_c  = &s_w[cur][co_l * CIC * 9];
        const int ci0 = ks * CIS;
        for (int ci = ci0; ci < ci0 + CIS; ++ci) {
            float w9[9];
#pragma unroll
            for (int k = 0; k < 9; ++k) w9[k] = sw_c[ci * 9 + k];
            const float* sp = sin_b + ci * IN_CH;
#pragma unroll
            for (int r = 0; r < RH; ++r) {
                float v[NV4 * 4];
#pragma unroll
                for (int q = 0; q < NV4; ++q)
                    *reinterpret_cast<float4*>(v + 4 * q) =
                        *reinterpret_cast<const float4*>(sp + r * SW + 4 * q);
#pragma unroll
                for (int kh = 0; kh < 3; ++kh) {
                    if (r - kh >= 0 && (r - kh) % STRIDE == 0 && (r - kh) / STRIDE < TH) {
                        const int ii = (r - kh) / STRIDE;
#pragma unroll
                        for (int kw = 0; kw < 3; ++kw)
#pragma unroll
                            for (int j = 0; j < TW; ++j)
                                acc[ii * TW + j] = fmaf(w9[kh * 3 + kw],
                                                        v[j * STRIDE + kw],
                                                        acc[ii * TW + j]);
                    }
                }
            }
        }
        __syncthreads();
    }

    // K-split reduction (scratch overlays staging buffers, now dead)
    if (KS > 1) {
        if (ks > 0) {
#pragma unroll
            for (int i = 0; i < THW; ++i)
                s_red[(ks - 1) * SNT * THW + stid * THW + i] = acc[i];
        }
        __syncthreads();
        if (ks != 0) return;
#pragma unroll
        for (int k = 1; k < KS; ++k)
#pragma unroll
            for (int i = 0; i < THW; ++i)
                acc[i] += s_red[(k - 1) * SNT * THW + stid * THW + i];
    }

    // fused 1x1-s2 shortcut conv
    float rsum[THW];
    if (SC_CI > 0) {
#pragma unroll
        for (int i = 0; i < THW; ++i) rsum[i] = 0.0f;
        const float* wp = sc_w + (size_t)co * SC_CI;
        for (int ci = 0; ci < SC_CI; ++ci) {
            float wv = __ldg(wp + ci);
            const float* ip = sc_in + ((size_t)b * SC_CI + ci) * (4 * HO * WO);
#pragma unroll
            for (int i = 0; i < TH; ++i)
#pragma unroll
                for (int j = 0; j < TW; ++j)
                    rsum[i * TW + j] = fmaf(wv,
                        __ldg(ip + (2 * (oh0 + i)) * (2 * WO) + 2 * (ow0 + j)),
                        rsum[i * TW + j]);
        }
    }

    const float thr  = __ldg(thr_a + lidx);
    const float leak = __ldg(leak_a + lidx);

    float s_tile[THW];
#pragma unroll
    for (int i = 0; i < TH; ++i) {
#pragma unroll
        for (int j = 0; j < TW; ++j) {
            size_t oi = (((size_t)b * CO + co) * HO + oh0 + i) * WO + ow0 + j;
            float d = acc[i * TW + j];
            if (SC_CI > 0) d += rsum[i * TW + j];
            else if (res) d += __ldg(res + oi);
            if (mem == nullptr) { out[oi] = d; continue; }
            float m = fmaf(leak, mem[oi], d);
            float mth = m / thr - 1.0f;
            float s = (mth > 0.0f) ? 1.0f : 0.0f;
            mem[oi] = m - thr * s;
            if (POOL) s_tile[i * TW + j] = s;
            else out[oi] = mask ? s * __ldg(mask + oi) : s;
        }
    }
    if (POOL && mem != nullptr) {
        constexpr int HOP = HO / 2, WOP = WO / 2;
#pragma unroll
        for (int i2 = 0; i2 < TH / 2; ++i2)
#pragma unroll
            for (int j2 = 0; j2 < TW / 2; ++j2) {
                float sum = s_tile[(2 * i2) * TW + 2 * j2] +
                            s_tile[(2 * i2) * TW + 2 * j2 + 1] +
                            s_tile[(2 * i2 + 1) * TW + 2 * j2] +
                            s_tile[(2 * i2 + 1) * TW + 2 * j2 + 1];
                out[(((size_t)b * CO + co) * HOP + (oh0 >> 1) + i2) * WOP +
                    (ow0 >> 1) + j2] = 0.25f * sum;
            }
    }
}

// FC accumulate: out[b,j] += sum_k in[b,k] * wfc[j,k].  One warp per output.
__global__ __launch_bounds__(256)
void fc_acc(const float* __restrict__ in, const float* __restrict__ wfc,
            float* __restrict__ out) {
    int gw = (blockIdx.x * blockDim.x + threadIdx.x) >> 5;
    int lane = threadIdx.x & 31;
    if (gw >= B * 10) return;
    int b = gw / 10, j = gw % 10;
    const float* x = in + (size_t)b * 2048;
    const float* w = wfc + (size_t)j * 2048;
    float s = 0.f;
    for (int k = lane; k < 2048; k += 32) s = fmaf(x[k], w[k], s);
#pragma unroll
    for (int o = 16; o; o >>= 1) s += __shfl_down_sync(0xffffffffu, s, o);
    if (lane == 0) out[b * 10 + j] += s;
}

// -------------------------- host-side orchestration ------------------------

extern "C" void kernel_launch(void* const* d_in, const int* in_sizes, int n_in,
                              void* d_out, int out_size) {
    const float* x      = (const float*)d_in[0];
    const float* w_pre0 = (const float*)d_in[1];
    const float* w_pre1 = (const float*)d_in[2];
    const float* w_pre2 = (const float*)d_in[3];
    const float* w1a    = (const float*)d_in[4];
    const float* w1b    = (const float*)d_in[5];
    const float* w2a    = (const float*)d_in[6];
    const float* w2b    = (const float*)d_in[7];
    const float* w2i    = (const float*)d_in[8];
    const float* w3a    = (const float*)d_in[9];
    const float* w3b    = (const float*)d_in[10];
    const float* w3i    = (const float*)d_in[11];
    const float* w4a    = (const float*)d_in[12];
    const float* w4b    = (const float*)d_in[13];
    const float* w4i    = (const float*)d_in[14];
    const float* w_fc   = (const float*)d_in[15];
    const float* thr    = (const float*)d_in[16];
    const float* leak   = (const float*)d_in[17];
    const float* mask2  = (const float*)d_in[18];
    const float* mask5  = (const float*)d_in[19];
    const float* mask9  = (const float*)d_in[20];
    const float* mask11 = (const float*)d_in[21];
    const float* mask13 = (const float*)d_in[22];
    const float* mask15 = (const float*)d_in[23];

    float *pm, *pA, *pB, *pC, *pD;
    cudaGetSymbolAddress((void**)&pm, g_mem);
    cudaGetSymbolAddress((void**)&pA, g_A);
    cudaGetSymbolAddress((void**)&pB, g_B);
    cudaGetSymbolAddress((void**)&pC, g_C);
    cudaGetSymbolAddress((void**)&pD, g_D);

    float* m0  = pm + OFF_M0;
    float* m1  = pm + OFF_M1;
    float* m2  = pm + OFF_M2;
    float* m3  = pm + OFF_M3;
    float* m4  = pm + OFF_M4;
    float* m5  = pm + OFF_M5;
    float* m6  = pm + OFF_M6;
    float* m7  = pm + OFF_M7;
    float* m8  = pm + OFF_M8;
    float* m9  = pm + OFF_M9;
    float* m10 = pm + OFF_M10;

    zero_kernel<<<(MEM_TOTAL + 255) / 256, 256>>>(pm, (int)MEM_TOTAL);
    zero_kernel<<<2, 256>>>((float*)d_out, out_size);

    // hoisted: delta0 = conv(x, w_pre0), constant across timesteps
    conv_fused<32, 3, 64, 1, 3, 4, 4, 4, 1, 256, 0, 0, 1><<<512, 256>>>(
        x, w_pre0, nullptr, nullptr, nullptr, nullptr, nullptr, pD, thr, leak, 0);

    for (int t = 0; t < TSTEPS; ++t) {
        // layer 0: elementwise LIF on precomputed delta (float4)
        lif0_kernel<<<2048, 256>>>((const float4*)pD, (float4*)m0,
                                   (const float4*)mask2, (float4*)pA, thr + 0, leak + 0);

        // pre-process convs (32x32, 64ch); pre2 fuses the 2x2 avgpool
        conv_fused<32, 64, 64, 1, 4, 4, 4, 4, 1, 256, 0, 0, 1><<<512, 256>>>(
            pA, w_pre1, nullptr, mask5, nullptr, nullptr, m1, pB, thr, leak, 1);
        conv_fused<32, 64, 64, 1, 4, 4, 4, 4, 1, 256, 0, 1, 1><<<512, 256>>>(
            pB, w_pre2, nullptr, nullptr, nullptr, nullptr, m2, pC, thr, leak, 2);

        // layer1 (identity shortcut), 16x16x64 — R7 grid/tiling, NT 256->512
        conv_fused<16, 64, 64, 1, 8, 4, 4, 16, 1, 512, 0, 0, 2><<<128, 512>>>(
            pC, w1a, nullptr, mask9, nullptr, nullptr, m3, pA, thr, leak, 3);
        conv_fused<16, 64, 64, 1, 8, 4, 4, 16, 1, 512, 0, 0, 2><<<128, 512>>>(
            pA, w1b, pC, nullptr, nullptr, nullptr, m4, pB, thr, leak, 4);

        // layer2 — R7 grids, NT doubled via KS=2
        conv_fused<16, 64, 128, 2, 4, 2, 4, 16, 2, 512, 0, 0, 2><<<128, 512>>>(
            pB, w2a, nullptr, mask11, nullptr, nullptr, m5, pC, thr, leak, 5);
        conv_fused<8, 128, 128, 1, 8, 4, 4, 16, 2, 256, 64, 0, 2><<<128, 256>>>(
            pC, w2b, nullptr, nullptr, pB, w2i, m6, pA, thr, leak, 6);

        // layer3
        conv_fused<8, 128, 256, 2, 8, 2, 2, 16, 2, 256, 0, 0, 2><<<256, 256>>>(
            pA, w3a, nullptr, mask13, nullptr, nullptr, m7, pB, thr, leak, 7);
        conv_fused<4, 256, 256, 1, 8, 2, 4, 32, 2, 256, 128, 0, 2><<<128, 256>>>(
            pB, w3b, nullptr, nullptr, pA, w3i, m8, pC, thr, leak, 8);

        // layer4
        conv_fused<4, 256, 512, 2, 8, 2, 2, 32, 4, 256, 0, 0, 2><<<128, 256>>>(
            pC, w4a, nullptr, mask15, nullptr, nullptr, m9, pB, thr, leak, 9);
        conv_fused<2, 512, 512, 1, 16, 2, 2, 32, 4, 256, 256, 0, 2><<<128, 256>>>(
            pB, w4b, nullptr, nullptr, pC, w4i, m10, pA, thr, leak, 10);

        // classifier accumulation
        fc_acc<<<40, 256>>>(pA, w_fc, (float*)d_out);
    }
}

// round 11
// speedup vs baseline: 1.0124x; 1.0079x over previous
#include <cuda_runtime.h>
#include <cuda_pipeline.h>

// ---------------------------------------------------------------------------
// SNN ResNet forward, 8 timesteps, B=32. fp32 smem-tiled convs with cp.async
// double buffering (R7 structure); deep layers use finer spatial tiles to
// double warps/block at identical grids/staging. Fused LIF / masks /
// residuals / 1x1-s2 shortcuts / avgpool. Layer-0 conv hoisted.
// ---------------------------------------------------------------------------

#define B 32
#define TSTEPS 8

#define OFF_M0  0u
#define OFF_M1  2097152u
#define OFF_M2  4194304u
#define OFF_M3  6291456u
#define OFF_M4  6815744u
#define OFF_M5  7340032u
#define OFF_M6  7602176u
#define OFF_M7  7864320u
#define OFF_M8  7995392u
#define OFF_M9  8126464u
#define OFF_M10 8192000u
#define MEM_TOTAL 8257536u

__device__ float g_mem[MEM_TOTAL];
__device__ float g_A[2097152];
__device__ float g_B[2097152];
__device__ float g_C[2097152];
__device__ float g_D[2097152];   // precomputed conv(x, w_pre0)

__global__ void zero_kernel(float* __restrict__ p, int n) {
    int i = blockIdx.x * blockDim.x + threadIdx.x;
    if (i < n) p[i] = 0.0f;
}

// elementwise LIF for layer 0, float4-vectorized (delta precomputed)
__global__ __launch_bounds__(256)
void lif0_kernel(const float4* __restrict__ delta, float4* __restrict__ mem,
                 const float4* __restrict__ mask, float4* __restrict__ out,
                 const float* __restrict__ thr_a, const float* __restrict__ leak_a) {
    int i = blockIdx.x * blockDim.x + threadIdx.x;
    float thr = __ldg(thr_a), leak = __ldg(leak_a);
    float4 d = __ldg(delta + i);
    float4 mm = mem[i];
    float4 mk = __ldg(mask + i);
    float4 o, nm;
    { float m = fmaf(leak, mm.x, d.x); float s = (m / thr > 1.0f) ? 1.0f : 0.0f;
      nm.x = m - thr * s; o.x = s * mk.x; }
    { float m = fmaf(leak, mm.y, d.y); float s = (m / thr > 1.0f) ? 1.0f : 0.0f;
      nm.y = m - thr * s; o.y = s * mk.y; }
    { float m = fmaf(leak, mm.z, d.z); float s = (m / thr > 1.0f) ? 1.0f : 0.0f;
      nm.z = m - thr * s; o.z = s * mk.z; }
    { float m = fmaf(leak, mm.w, d.w); float s = (m / thr > 1.0f) ? 1.0f : 0.0f;
      nm.w = m - thr * s; o.w = s * mk.w; }
    mem[i] = nm;
    out[i] = o;
}

// ---------------------------------------------------------------------------
// Fused 3x3 conv (pad=1) + (residual | fused 1x1-s2 shortcut) + LIF + mask
// (+ optional fused 2x2 avgpool). Double-buffered cp.async chunk staging.
// mem == nullptr  =>  raw conv output (no LIF), used for hoisted layer 0.
// ---------------------------------------------------------------------------
template<int H, int CI, int CO, int STRIDE, int CIC, int TH, int TW,
         int CO_T, int B_T, int NT, int SC_CI, int POOL>
__global__ __launch_bounds__(NT)
void conv_fused(const float* __restrict__ in, const float* __restrict__ wgt,
                const float* __restrict__ res, const float* __restrict__ mask,
                const float* __restrict__ sc_in, const float* __restrict__ sc_w,
                float* __restrict__ mem, float* __restrict__ out,
                const float* __restrict__ thr_a, const float* __restrict__ leak_a,
                int lidx) {
    constexpr int HO = H / STRIDE;
    constexpr int WO = HO;
    constexpr int TILESH = HO / TH;
    constexpr int TILESW = WO / TW;
    constexpr int TILES = TILESH * TILESW;
    static_assert(TILES * CO_T * B_T == NT, "thread count mismatch");
    static_assert((TW * STRIDE) % 4 == 0 || TILESW == 1, "LDS.128 alignment");
    constexpr int RH = (TH - 1) * STRIDE + 3;
    constexpr int RW = (TW - 1) * STRIDE + 3;
    constexpr int NV4 = (RW + 3) / 4;
    constexpr int SWMIN = (H + 2 > NV4 * 4) ? (H + 2) : (NV4 * 4);
    constexpr int SW = ((SWMIN + 3) / 4) * 4;   // smem row stride (interior col 1)
    constexpr int HI2 = H + 2;
    constexpr int IN_CH = HI2 * SW;
    constexpr int IN_IMG = CIC * IN_CH;
    constexpr int IN_TOT = B_T * IN_IMG;
    constexpr int W_TOT = CO_T * CIC * 9;
    constexpr int CHUNKS = CI / CIC;
    constexpr int THW = TH * TW;

    __shared__ alignas(16) float s_in[2][IN_TOT];
    __shared__ alignas(16) float s_w[2][W_TOT];

    const int tid = threadIdx.x;
    const int tile = tid % TILES;
    const int co_l = (tid / TILES) % CO_T;
    const int b_l  = tid / (TILES * CO_T);
    const int co_g = blockIdx.x % (CO / CO_T);
    const int b_g  = blockIdx.x / (CO / CO_T);
    const int b  = b_g * B_T + b_l;
    const int co = co_g * CO_T + co_l;
    const int oh0 = (tile / TILESW) * TH;
    const int ow0 = (tile % TILESW) * TW;

    // zero both input buffers once: halo / padding stays zero for all chunks
    {
        const float4 z4 = make_float4(0.f, 0.f, 0.f, 0.f);
        for (int i = tid * 4; i < IN_TOT; i += NT * 4) {
            *reinterpret_cast<float4*>(&s_in[0][i]) = z4;
            *reinterpret_cast<float4*>(&s_in[1][i]) = z4;
        }
    }
    __syncthreads();

    auto stage = [&](int buf, int cc) {
        constexpr int NE = B_T * CIC * H * H;
        for (int e = tid; e < NE; e += NT) {
            const int wq = e % H;
            int r = e / H;
            const int h = r % H; r /= H;
            const int ci = r % CIC;
            const int bl = r / CIC;
            const float* src = in + (((size_t)(b_g * B_T + bl) * CI + cc * CIC + ci) * H + h) * H + wq;
            __pipeline_memcpy_async(&s_in[buf][bl * IN_IMG + ci * IN_CH + (h + 1) * SW + 1 + wq],
                                    src, 4);
        }
        for (int e = tid; e < W_TOT; e += NT) {
            const int rem = e % (CIC * 9);
            const int col = e / (CIC * 9);
            const float* src = wgt + ((size_t)(co_g * CO_T + col) * CI + cc * CIC) * 9 + rem;
            __pipeline_memcpy_async(&s_w[buf][col * CIC * 9 + rem], src, 4);
        }
    };

    float acc[THW];
#pragma unroll
    for (int i = 0; i < THW; ++i) acc[i] = 0.0f;

    stage(0, 0);
    __pipeline_commit();

    for (int cc = 0; cc < CHUNKS; ++cc) {
        const int cur = cc & 1;
        if (cc + 1 < CHUNKS) {
            stage(cur ^ 1, cc + 1);
            __pipeline_commit();
            __pipeline_wait_prior(1);
        } else {
            __pipeline_wait_prior(0);
        }
        __syncthreads();

        const float* sin_b = &s_in[cur][b_l * IN_IMG + (oh0 * STRIDE) * SW + ow0 * STRIDE];
        const float* sw_c  = &s_w[cur][co_l * CIC * 9];
        for (int ci = 0; ci < CIC; ++ci) {
            float w9[9];
#pragma unroll
            for (int k = 0; k < 9; ++k) w9[k] = sw_c[ci * 9 + k];
            const float* sp = sin_b + ci * IN_CH;
#pragma unroll
            for (int r = 0; r < RH; ++r) {
                float v[NV4 * 4];
#pragma unroll
                for (int q = 0; q < NV4; ++q)
                    *reinterpret_cast<float4*>(v + 4 * q) =
                        *reinterpret_cast<const float4*>(sp + r * SW + 4 * q);
#pragma unroll
                for (int kh = 0; kh < 3; ++kh) {
                    if (r - kh >= 0 && (r - kh) % STRIDE == 0 && (r - kh) / STRIDE < TH) {
                        const int ii = (r - kh) / STRIDE;
#pragma unroll
                        for (int kw = 0; kw < 3; ++kw)
#pragma unroll
                            for (int j = 0; j < TW; ++j)
                                acc[ii * TW + j] = fmaf(w9[kh * 3 + kw],
                                                        v[j * STRIDE + kw],
                                                        acc[ii * TW + j]);
                    }
                }
            }
        }
        __syncthreads();
    }

    // fused 1x1-s2 shortcut conv
    float rsum[THW];
    if (SC_CI > 0) {
#pragma unroll
        for (int i = 0; i < THW; ++i) rsum[i] = 0.0f;
        const float* wp = sc_w + (size_t)co * SC_CI;
        for (int ci = 0; ci < SC_CI; ++ci) {
            float wv = __ldg(wp + ci);
            const float* ip = sc_in + ((size_t)b * SC_CI + ci) * (4 * HO * WO);
#pragma unroll
            for (int i = 0; i < TH; ++i)
#pragma unroll
                for (int j = 0; j < TW; ++j)
                    rsum[i * TW + j] = fmaf(wv,
                        __ldg(ip + (2 * (oh0 + i)) * (2 * WO) + 2 * (ow0 + j)),
                        rsum[i * TW + j]);
        }
    }

    const float thr  = __ldg(thr_a + lidx);
    const float leak = __ldg(leak_a + lidx);

    float s_tile[THW];
#pragma unroll
    for (int i = 0; i < TH; ++i) {
#pragma unroll
        for (int j = 0; j < TW; ++j) {
            size_t oi = (((size_t)b * CO + co) * HO + oh0 + i) * WO + ow0 + j;
            float d = acc[i * TW + j];
            if (SC_CI > 0) d += rsum[i * TW + j];
            else if (res) d += __ldg(res + oi);
            if (mem == nullptr) { out[oi] = d; continue; }
            float m = fmaf(leak, mem[oi], d);
            float mth = m / thr - 1.0f;
            float s = (mth > 0.0f) ? 1.0f : 0.0f;
            mem[oi] = m - thr * s;
            if (POOL) s_tile[i * TW + j] = s;
            else out[oi] = mask ? s * __ldg(mask + oi) : s;
        }
    }
    if (POOL && mem != nullptr) {
        constexpr int HOP = HO / 2, WOP = WO / 2;
#pragma unroll
        for (int i2 = 0; i2 < TH / 2; ++i2)
#pragma unroll
            for (int j2 = 0; j2 < TW / 2; ++j2) {
                float sum = s_tile[(2 * i2) * TW + 2 * j2] +
                            s_tile[(2 * i2) * TW + 2 * j2 + 1] +
                            s_tile[(2 * i2 + 1) * TW + 2 * j2] +
                            s_tile[(2 * i2 + 1) * TW + 2 * j2 + 1];
                out[(((size_t)b * CO + co) * HOP + (oh0 >> 1) + i2) * WOP +
                    (ow0 >> 1) + j2] = 0.25f * sum;
            }
    }
}

// FC accumulate: out[b,j] += sum_k in[b,k] * wfc[j,k].  One warp per output.
__global__ __launch_bounds__(256)
void fc_acc(const float* __restrict__ in, const float* __restrict__ wfc,
            float* __restrict__ out) {
    int gw = (blockIdx.x * blockDim.x + threadIdx.x) >> 5;
    int lane = threadIdx.x & 31;
    if (gw >= B * 10) return;
    int b = gw / 10, j = gw % 10;
    const float* x = in + (size_t)b * 2048;
    const float* w = wfc + (size_t)j * 2048;
    float s = 0.f;
    for (int k = lane; k < 2048; k += 32) s = fmaf(x[k], w[k], s);
#pragma unroll
    for (int o = 16; o; o >>= 1) s += __shfl_down_sync(0xffffffffu, s, o);
    if (lane == 0) out[b * 10 + j] += s;
}

// -------------------------- host-side orchestration ------------------------

extern "C" void kernel_launch(void* const* d_in, const int* in_sizes, int n_in,
                              void* d_out, int out_size) {
    const float* x      = (const float*)d_in[0];
    const float* w_pre0 = (const float*)d_in[1];
    const float* w_pre1 = (const float*)d_in[2];
    const float* w_pre2 = (const float*)d_in[3];
    const float* w1a    = (const float*)d_in[4];
    const float* w1b    = (const float*)d_in[5];
    const float* w2a    = (const float*)d_in[6];
    const float* w2b    = (const float*)d_in[7];
    const float* w2i    = (const float*)d_in[8];
    const float* w3a    = (const float*)d_in[9];
    const float* w3b    = (const float*)d_in[10];
    const float* w3i    = (const float*)d_in[11];
    const float* w4a    = (const float*)d_in[12];
    const float* w4b    = (const float*)d_in[13];
    const float* w4i    = (const float*)d_in[14];
    const float* w_fc   = (const float*)d_in[15];
    const float* thr    = (const float*)d_in[16];
    const float* leak   = (const float*)d_in[17];
    const float* mask2  = (const float*)d_in[18];
    const float* mask5  = (const float*)d_in[19];
    const float* mask9  = (const float*)d_in[20];
    const float* mask11 = (const float*)d_in[21];
    const float* mask13 = (const float*)d_in[22];
    const float* mask15 = (const float*)d_in[23];

    float *pm, *pA, *pB, *pC, *pD;
    cudaGetSymbolAddress((void**)&pm, g_mem);
    cudaGetSymbolAddress((void**)&pA, g_A);
    cudaGetSymbolAddress((void**)&pB, g_B);
    cudaGetSymbolAddress((void**)&pC, g_C);
    cudaGetSymbolAddress((void**)&pD, g_D);

    float* m0  = pm + OFF_M0;
    float* m1  = pm + OFF_M1;
    float* m2  = pm + OFF_M2;
    float* m3  = pm + OFF_M3;
    float* m4  = pm + OFF_M4;
    float* m5  = pm + OFF_M5;
    float* m6  = pm + OFF_M6;
    float* m7  = pm + OFF_M7;
    float* m8  = pm + OFF_M8;
    float* m9  = pm + OFF_M9;
    float* m10 = pm + OFF_M10;

    zero_kernel<<<(MEM_TOTAL + 255) / 256, 256>>>(pm, (int)MEM_TOTAL);
    zero_kernel<<<2, 256>>>((float*)d_out, out_size);

    // hoisted: delta0 = conv(x, w_pre0), constant across timesteps
    conv_fused<32, 3, 64, 1, 3, 4, 4, 4, 1, 256, 0, 0><<<512, 256>>>(
        x, w_pre0, nullptr, nullptr, nullptr, nullptr, nullptr, pD, thr, leak, 0);

    for (int t = 0; t < TSTEPS; ++t) {
        // layer 0: elementwise LIF on precomputed delta (float4)
        lif0_kernel<<<2048, 256>>>((const float4*)pD, (float4*)m0,
                                   (const float4*)mask2, (float4*)pA, thr + 0, leak + 0);

        // pre-process convs (32x32, 64ch); pre2 fuses the 2x2 avgpool
        conv_fused<32, 64, 64, 1, 4, 4, 4, 4, 1, 256, 0, 0><<<512, 256>>>(
            pA, w_pre1, nullptr, mask5, nullptr, nullptr, m1, pB, thr, leak, 1);
        conv_fused<32, 64, 64, 1, 4, 4, 4, 4, 1, 256, 0, 1><<<512, 256>>>(
            pB, w_pre2, nullptr, nullptr, nullptr, nullptr, m2, pC, thr, leak, 2);

        // layer1 (identity shortcut), 16x16x64: finer tiles -> NT=512
        conv_fused<16, 64, 64, 1, 8, 2, 4, 16, 1, 512, 0, 0><<<128, 512>>>(
            pC, w1a, nullptr, mask9, nullptr, nullptr, m3, pA, thr, leak, 3);
        conv_fused<16, 64, 64, 1, 8, 2, 4, 16, 1, 512, 0, 0><<<128, 512>>>(
            pA, w1b, pC, nullptr, nullptr, nullptr, m4, pB, thr, leak, 4);

        // layer2: 16x16x64 -> 8x8x128 (fused 1x1-s2 shortcut in conv-b)
        conv_fused<16, 64, 128, 2, 4, 1, 4, 16, 2, 512, 0, 0><<<128, 512>>>(
            pB, w2a, nullptr, mask11, nullptr, nullptr, m5, pC, thr, leak, 5);
        conv_fused<8, 128, 128, 1, 8, 2, 4, 16, 2, 256, 64, 0><<<128, 256>>>(
            pC, w2b, nullptr, nullptr, pB, w2i, m6, pA, thr, leak, 6);

        // layer3: 8x8x128 -> 4x4x256
        conv_fused<8, 128, 256, 2, 8, 1, 2, 16, 2, 256, 0, 0><<<256, 256>>>(
            pA, w3a, nullptr, mask13, nullptr, nullptr, m7, pB, thr, leak, 7);
        conv_fused<4, 256, 256, 1, 8, 1, 4, 32, 2, 256, 128, 0><<<128, 256>>>(
            pB, w3b, nullptr, nullptr, pA, w3i, m8, pC, thr, leak, 8);

        // layer4: 4x4x256 -> 2x2x512
        conv_fused<4, 256, 512, 2, 8, 1, 2, 32, 4, 256, 0, 0><<<128, 256>>>(
            pC, w4a, nullptr, mask15, nullptr, nullptr, m9, pB, thr, leak, 9);
        conv_fused<2, 512, 512, 1, 16, 1, 2, 32, 4, 256, 256, 0><<<128, 256>>>(
            pB, w4b, nullptr, nullptr, pC, w4i, m10, pA, thr, leak, 10);

        // classifier accumulation
        fc_acc<<<40, 256>>>(pA, w_fc, (float*)d_out);
    }
}

// round 12
// speedup vs baseline: 1.0915x; 1.0781x over previous
#include <cuda_runtime.h>
#include <cuda_pipeline.h>

// ---------------------------------------------------------------------------
// SNN ResNet forward, 8 timesteps, B=32. fp32 smem-tiled convs with cp.async
// double buffering (R7 inner loop, unchanged). NEW: the pre-process chain of
// step t+1 runs CONCURRENTLY with the deep chain of step t on a forked
// capture stream (they touch disjoint state). Fused LIF / masks / residuals /
// 1x1-s2 shortcuts / avgpool. Layer-0 conv hoisted.
// ---------------------------------------------------------------------------

#define B 32
#define TSTEPS 8

#define OFF_M0  0u
#define OFF_M1  2097152u
#define OFF_M2  4194304u
#define OFF_M3  6291456u
#define OFF_M4  6815744u
#define OFF_M5  7340032u
#define OFF_M6  7602176u
#define OFF_M7  7864320u
#define OFF_M8  7995392u
#define OFF_M9  8126464u
#define OFF_M10 8192000u
#define MEM_TOTAL 8257536u

__device__ float g_mem[MEM_TOTAL];
__device__ float g_A[2097152];    // pre: lif0 spikes (32x32x64)
__device__ float g_B[2097152];    // pre: pre1 spikes (32x32x64)
__device__ float g_D[2097152];    // precomputed conv(x, w_pre0)
__device__ float g_C[524288];     // deep scratch
__device__ float g_E[524288];     // deep scratch
__device__ float g_F[524288];     // deep scratch
__device__ float g_Q0[524288];    // pre2 pooled output, even steps
__device__ float g_Q1[524288];    // pre2 pooled output, odd steps

__global__ void zero_kernel(float* __restrict__ p, int n) {
    int i = blockIdx.x * blockDim.x + threadIdx.x;
    if (i < n) p[i] = 0.0f;
}

// elementwise LIF for layer 0, float4-vectorized (delta precomputed)
__global__ __launch_bounds__(256)
void lif0_kernel(const float4* __restrict__ delta, float4* __restrict__ mem,
                 const float4* __restrict__ mask, float4* __restrict__ out,
                 const float* __restrict__ thr_a, const float* __restrict__ leak_a) {
    int i = blockIdx.x * blockDim.x + threadIdx.x;
    float thr = __ldg(thr_a), leak = __ldg(leak_a);
    float4 d = __ldg(delta + i);
    float4 mm = mem[i];
    float4 mk = __ldg(mask + i);
    float4 o, nm;
    { float m = fmaf(leak, mm.x, d.x); float s = (m / thr > 1.0f) ? 1.0f : 0.0f;
      nm.x = m - thr * s; o.x = s * mk.x; }
    { float m = fmaf(leak, mm.y, d.y); float s = (m / thr > 1.0f) ? 1.0f : 0.0f;
      nm.y = m - thr * s; o.y = s * mk.y; }
    { float m = fmaf(leak, mm.z, d.z); float s = (m / thr > 1.0f) ? 1.0f : 0.0f;
      nm.z = m - thr * s; o.z = s * mk.z; }
    { float m = fmaf(leak, mm.w, d.w); float s = (m / thr > 1.0f) ? 1.0f : 0.0f;
      nm.w = m - thr * s; o.w = s * mk.w; }
    mem[i] = nm;
    out[i] = o;
}

// ---------------------------------------------------------------------------
// Fused 3x3 conv (pad=1) + (residual | fused 1x1-s2 shortcut) + LIF + mask
// (+ optional fused 2x2 avgpool). Double-buffered cp.async chunk staging.
// mem == nullptr  =>  raw conv output (no LIF), used for hoisted layer 0.
// (Identical to the best R7 kernel.)
// ---------------------------------------------------------------------------
template<int H, int CI, int CO, int STRIDE, int CIC, int TH, int TW,
         int CO_T, int B_T, int NT, int SC_CI, int POOL>
__global__ __launch_bounds__(NT)
void conv_fused(const float* __restrict__ in, const float* __restrict__ wgt,
                const float* __restrict__ res, const float* __restrict__ mask,
                const float* __restrict__ sc_in, const float* __restrict__ sc_w,
                float* __restrict__ mem, float* __restrict__ out,
                const float* __restrict__ thr_a, const float* __restrict__ leak_a,
                int lidx) {
    constexpr int HO = H / STRIDE;
    constexpr int WO = HO;
    constexpr int TILESH = HO / TH;
    constexpr int TILESW = WO / TW;
    constexpr int TILES = TILESH * TILESW;
    static_assert(TILES * CO_T * B_T == NT, "thread count mismatch");
    static_assert((TW * STRIDE) % 4 == 0 || TILESW == 1, "LDS.128 alignment");
    constexpr int RH = (TH - 1) * STRIDE + 3;
    constexpr int RW = (TW - 1) * STRIDE + 3;
    constexpr int NV4 = (RW + 3) / 4;
    constexpr int SWMIN = (H + 2 > NV4 * 4) ? (H + 2) : (NV4 * 4);
    constexpr int SW = ((SWMIN + 3) / 4) * 4;   // smem row stride (interior col 1)
    constexpr int HI2 = H + 2;
    constexpr int IN_CH = HI2 * SW;
    constexpr int IN_IMG = CIC * IN_CH;
    constexpr int IN_TOT = B_T * IN_IMG;
    constexpr int W_TOT = CO_T * CIC * 9;
    constexpr int CHUNKS = CI / CIC;
    constexpr int THW = TH * TW;

    __shared__ alignas(16) float s_in[2][IN_TOT];
    __shared__ alignas(16) float s_w[2][W_TOT];

    const int tid = threadIdx.x;
    const int tile = tid % TILES;
    const int co_l = (tid / TILES) % CO_T;
    const int b_l  = tid / (TILES * CO_T);
    const int co_g = blockIdx.x % (CO / CO_T);
    const int b_g  = blockIdx.x / (CO / CO_T);
    const int b  = b_g * B_T + b_l;
    const int co = co_g * CO_T + co_l;
    const int oh0 = (tile / TILESW) * TH;
    const int ow0 = (tile % TILESW) * TW;

    // zero both input buffers once: halo / padding stays zero for all chunks
    {
        const float4 z4 = make_float4(0.f, 0.f, 0.f, 0.f);
        for (int i = tid * 4; i < IN_TOT; i += NT * 4) {
            *reinterpret_cast<float4*>(&s_in[0][i]) = z4;
            *reinterpret_cast<float4*>(&s_in[1][i]) = z4;
        }
    }
    __syncthreads();

    auto stage = [&](int buf, int cc) {
        constexpr int NE = B_T * CIC * H * H;
        for (int e = tid; e < NE; e += NT) {
            const int wq = e % H;
            int r = e / H;
            const int h = r % H; r /= H;
            const int ci = r % CIC;
            const int bl = r / CIC;
            const float* src = in + (((size_t)(b_g * B_T + bl) * CI + cc * CIC + ci) * H + h) * H + wq;
            __pipeline_memcpy_async(&s_in[buf][bl * IN_IMG + ci * IN_CH + (h + 1) * SW + 1 + wq],
                                    src, 4);
        }
        for (int e = tid; e < W_TOT; e += NT) {
            const int rem = e % (CIC * 9);
            const int col = e / (CIC * 9);
            const float* src = wgt + ((size_t)(co_g * CO_T + col) * CI + cc * CIC) * 9 + rem;
            __pipeline_memcpy_async(&s_w[buf][col * CIC * 9 + rem], src, 4);
        }
    };

    float acc[THW];
#pragma unroll
    for (int i = 0; i < THW; ++i) acc[i] = 0.0f;

    stage(0, 0);
    __pipeline_commit();

    for (int cc = 0; cc < CHUNKS; ++cc) {
        const int cur = cc & 1;
        if (cc + 1 < CHUNKS) {
            stage(cur ^ 1, cc + 1);
            __pipeline_commit();
            __pipeline_wait_prior(1);
        } else {
            __pipeline_wait_prior(0);
        }
        __syncthreads();

        const float* sin_b = &s_in[cur][b_l * IN_IMG + (oh0 * STRIDE) * SW + ow0 * STRIDE];
        const float* sw_c  = &s_w[cur][co_l * CIC * 9];
        for (int ci = 0; ci < CIC; ++ci) {
            float w9[9];
#pragma unroll
            for (int k = 0; k < 9; ++k) w9[k] = sw_c[ci * 9 + k];
            const float* sp = sin_b + ci * IN_CH;
#pragma unroll
            for (int r = 0; r < RH; ++r) {
                float v[NV4 * 4];
#pragma unroll
                for (int q = 0; q < NV4; ++q)
                    *reinterpret_cast<float4*>(v + 4 * q) =
                        *reinterpret_cast<const float4*>(sp + r * SW + 4 * q);
#pragma unroll
                for (int kh = 0; kh < 3; ++kh) {
                    if (r - kh >= 0 && (r - kh) % STRIDE == 0 && (r - kh) / STRIDE < TH) {
                        const int ii = (r - kh) / STRIDE;
#pragma unroll
                        for (int kw = 0; kw < 3; ++kw)
#pragma unroll
                            for (int j = 0; j < TW; ++j)
                                acc[ii * TW + j] = fmaf(w9[kh * 3 + kw],
                                                        v[j * STRIDE + kw],
                                                        acc[ii * TW + j]);
                    }
                }
            }
        }
        __syncthreads();
    }

    // fused 1x1-s2 shortcut conv
    float rsum[THW];
    if (SC_CI > 0) {
#pragma unroll
        for (int i = 0; i < THW; ++i) rsum[i] = 0.0f;
        const float* wp = sc_w + (size_t)co * SC_CI;
        for (int ci = 0; ci < SC_CI; ++ci) {
            float wv = __ldg(wp + ci);
            const float* ip = sc_in + ((size_t)b * SC_CI + ci) * (4 * HO * WO);
#pragma unroll
            for (int i = 0; i < TH; ++i)
#pragma unroll
                for (int j = 0; j < TW; ++j)
                    rsum[i * TW + j] = fmaf(wv,
                        __ldg(ip + (2 * (oh0 + i)) * (2 * WO) + 2 * (ow0 + j)),
                        rsum[i * TW + j]);
        }
    }

    const float thr  = __ldg(thr_a + lidx);
    const float leak = __ldg(leak_a + lidx);

    float s_tile[THW];
#pragma unroll
    for (int i = 0; i < TH; ++i) {
#pragma unroll
        for (int j = 0; j < TW; ++j) {
            size_t oi = (((size_t)b * CO + co) * HO + oh0 + i) * WO + ow0 + j;
            float d = acc[i * TW + j];
            if (SC_CI > 0) d += rsum[i * TW + j];
            else if (res) d += __ldg(res + oi);
            if (mem == nullptr) { out[oi] = d; continue; }
            float m = fmaf(leak, mem[oi], d);
            float mth = m / thr - 1.0f;
            float s = (mth > 0.0f) ? 1.0f : 0.0f;
            mem[oi] = m - thr * s;
            if (POOL) s_tile[i * TW + j] = s;
            else out[oi] = mask ? s * __ldg(mask + oi) : s;
        }
    }
    if (POOL && mem != nullptr) {
        constexpr int HOP = HO / 2, WOP = WO / 2;
#pragma unroll
        for (int i2 = 0; i2 < TH / 2; ++i2)
#pragma unroll
            for (int j2 = 0; j2 < TW / 2; ++j2) {
                float sum = s_tile[(2 * i2) * TW + 2 * j2] +
                            s_tile[(2 * i2) * TW + 2 * j2 + 1] +
                            s_tile[(2 * i2 + 1) * TW + 2 * j2] +
                            s_tile[(2 * i2 + 1) * TW + 2 * j2 + 1];
                out[(((size_t)b * CO + co) * HOP + (oh0 >> 1) + i2) * WOP +
                    (ow0 >> 1) + j2] = 0.25f * sum;
            }
    }
}

// FC accumulate: out[b,j] += sum_k in[b,k] * wfc[j,k].  One warp per output.
__global__ __launch_bounds__(256)
void fc_acc(const float* __restrict__ in, const float* __restrict__ wfc,
            float* __restrict__ out) {
    int gw = (blockIdx.x * blockDim.x + threadIdx.x) >> 5;
    int lane = threadIdx.x & 31;
    if (gw >= B * 10) return;
    int b = gw / 10, j = gw % 10;
    const float* x = in + (size_t)b * 2048;
    const float* w = wfc + (size_t)j * 2048;
    float s = 0.f;
    for (int k = lane; k < 2048; k += 32) s = fmaf(x[k], w[k], s);
#pragma unroll
    for (int o = 16; o; o >>= 1) s += __shfl_down_sync(0xffffffffu, s, o);
    if (lane == 0) out[b * 10 + j] += s;
}

// -------------------------- host-side orchestration ------------------------

extern "C" void kernel_launch(void* const* d_in, const int* in_sizes, int n_in,
                              void* d_out, int out_size) {
    const float* x      = (const float*)d_in[0];
    const float* w_pre0 = (const float*)d_in[1];
    const float* w_pre1 = (const float*)d_in[2];
    const float* w_pre2 = (const float*)d_in[3];
    const float* w1a    = (const float*)d_in[4];
    const float* w1b    = (const float*)d_in[5];
    const float* w2a    = (const float*)d_in[6];
    const float* w2b    = (const float*)d_in[7];
    const float* w2i    = (const float*)d_in[8];
    const float* w3a    = (const float*)d_in[9];
    const float* w3b    = (const float*)d_in[10];
    const float* w3i    = (const float*)d_in[11];
    const float* w4a    = (const float*)d_in[12];
    const float* w4b    = (const float*)d_in[13];
    const float* w4i    = (const float*)d_in[14];
    const float* w_fc   = (const float*)d_in[15];
    const float* thr    = (const float*)d_in[16];
    const float* leak   = (const float*)d_in[17];
    const float* mask2  = (const float*)d_in[18];
    const float* mask5  = (const float*)d_in[19];
    const float* mask9  = (const float*)d_in[20];
    const float* mask11 = (const float*)d_in[21];
    const float* mask13 = (const float*)d_in[22];
    const float* mask15 = (const float*)d_in[23];

    float *pm, *pA, *pB, *pC, *pD, *pE, *pF, *pQ0, *pQ1;
    cudaGetSymbolAddress((void**)&pm, g_mem);
    cudaGetSymbolAddress((void**)&pA, g_A);
    cudaGetSymbolAddress((void**)&pB, g_B);
    cudaGetSymbolAddress((void**)&pC, g_C);
    cudaGetSymbolAddress((void**)&pD, g_D);
    cudaGetSymbolAddress((void**)&pE, g_E);
    cudaGetSymbolAddress((void**)&pF, g_F);
    cudaGetSymbolAddress((void**)&pQ0, g_Q0);
    cudaGetSymbolAddress((void**)&pQ1, g_Q1);

    float* m0  = pm + OFF_M0;
    float* m1  = pm + OFF_M1;
    float* m2  = pm + OFF_M2;
    float* m3  = pm + OFF_M3;
    float* m4  = pm + OFF_M4;
    float* m5  = pm + OFF_M5;
    float* m6  = pm + OFF_M6;
    float* m7  = pm + OFF_M7;
    float* m8  = pm + OFF_M8;
    float* m9  = pm + OFF_M9;
    float* m10 = pm + OFF_M10;

    // fork stream + events for pre-chain / deep-chain overlap
    cudaStream_t s1;
    cudaStreamCreateWithFlags(&s1, cudaStreamNonBlocking);
    cudaEvent_t evInit, evPre[TSTEPS], evL1[TSTEPS];
    cudaEventCreateWithFlags(&evInit, cudaEventDisableTiming);
    for (int t = 0; t < TSTEPS; ++t) {
        cudaEventCreateWithFlags(&evPre[t], cudaEventDisableTiming);
        cudaEventCreateWithFlags(&evL1[t], cudaEventDisableTiming);
    }

    zero_kernel<<<(MEM_TOTAL + 255) / 256, 256>>>(pm, (int)MEM_TOTAL);
    zero_kernel<<<2, 256>>>((float*)d_out, out_size);

    // hoisted: delta0 = conv(x, w_pre0), constant across timesteps
    conv_fused<32, 3, 64, 1, 3, 4, 4, 4, 1, 256, 0, 0><<<512, 256>>>(
        x, w_pre0, nullptr, nullptr, nullptr, nullptr, nullptr, pD, thr, leak, 0);

    // fork: pre-chain stream starts after init work
    cudaEventRecord(evInit, 0);
    cudaStreamWaitEvent(s1, evInit, 0);

    for (int t = 0; t < TSTEPS; ++t) {
        float* Q = (t & 1) ? pQ1 : pQ0;

        // ---------------- pre-chain (stream s1) ----------------
        lif0_kernel<<<2048, 256, 0, s1>>>((const float4*)pD, (float4*)m0,
                                          (const float4*)mask2, (float4*)pA,
                                          thr + 0, leak + 0);
        conv_fused<32, 64, 64, 1, 4, 4, 4, 4, 1, 256, 0, 0><<<512, 256, 0, s1>>>(
            pA, w_pre1, nullptr, mask5, nullptr, nullptr, m1, pB, thr, leak, 1);
        // Q[t&1] reuse: deep chain of step t-2 must have consumed it (layer1b)
        if (t >= 2) cudaStreamWaitEvent(s1, evL1[t - 2], 0);
        conv_fused<32, 64, 64, 1, 4, 4, 4, 4, 1, 256, 0, 1><<<512, 256, 0, s1>>>(
            pB, w_pre2, nullptr, nullptr, nullptr, nullptr, m2, Q, thr, leak, 2);
        cudaEventRecord(evPre[t], s1);

        // ---------------- deep chain (default stream) ----------------
        cudaStreamWaitEvent(0, evPre[t], 0);

        // layer1 (identity shortcut), 16x16x64
        conv_fused<16, 64, 64, 1, 8, 4, 4, 16, 1, 256, 0, 0><<<128, 256>>>(
            Q, w1a, nullptr, mask9, nullptr, nullptr, m3, pE, thr, leak, 3);
        conv_fused<16, 64, 64, 1, 8, 4, 4, 16, 1, 256, 0, 0><<<128, 256>>>(
            pE, w1b, Q, nullptr, nullptr, nullptr, m4, pC, thr, leak, 4);
        cudaEventRecord(evL1[t], 0);   // Q[t&1] free

        // layer2: 16x16x64 -> 8x8x128 (fused 1x1-s2 shortcut in conv-b)
        conv_fused<16, 64, 128, 2, 4, 2, 4, 16, 2, 256, 0, 0><<<128, 256>>>(
            pC, w2a, nullptr, mask11, nullptr, nullptr, m5, pE, thr, leak, 5);
        conv_fused<8, 128, 128, 1, 8, 4, 4, 16, 2, 128, 64, 0><<<128, 128>>>(
            pE, w2b, nullptr, nullptr, pC, w2i, m6, pF, thr, leak, 6);

        // layer3: 8x8x128 -> 4x4x256
        conv_fused<8, 128, 256, 2, 8, 2, 2, 16, 2, 128, 0, 0><<<256, 128>>>(
            pF, w3a, nullptr, mask13, nullptr, nullptr, m7, pE, thr, leak, 7);
        conv_fused<4, 256, 256, 1, 8, 2, 4, 32, 2, 128, 128, 0><<<128, 128>>>(
            pE, w3b, nullptr, nullptr, pF, w3i, m8, pC, thr, leak, 8);

        // layer4: 4x4x256 -> 2x2x512
        conv_fused<4, 256, 512, 2, 8, 2, 2, 32, 4, 128, 0, 0><<<128, 128>>>(
            pC, w4a, nullptr, mask15, nullptr, nullptr, m9, pE, thr, leak, 9);
        conv_fused<2, 512, 512, 1, 16, 2, 2, 32, 4, 128, 256, 0><<<128, 128>>>(
            pE, w4b, nullptr, nullptr, pC, w4i, m10, pF, thr, leak, 10);

        // classifier accumulation
        fc_acc<<<40, 256>>>(pF, w_fc, (float*)d_out);
    }
}

// round 13
// speedup vs baseline: 1.3136x; 1.2035x over previous
#include <cuda_runtime.h>
#include <cuda_pipeline.h>

// ---------------------------------------------------------------------------
// SNN ResNet forward, 8 timesteps, B=32. fp32 smem-tiled convs with cp.async
// double buffering. Weight smem stride padded to odd (CIC*9+1) to kill the
// 2..16-way bank conflicts on per-lane weight loads in the deep layers.
// Fused LIF / masks / residuals / 1x1-s2 shortcuts / avgpool; layer-0 hoisted.
// ---------------------------------------------------------------------------

#define B 32
#define TSTEPS 8

#define OFF_M0  0u
#define OFF_M1  2097152u
#define OFF_M2  4194304u
#define OFF_M3  6291456u
#define OFF_M4  6815744u
#define OFF_M5  7340032u
#define OFF_M6  7602176u
#define OFF_M7  7864320u
#define OFF_M8  7995392u
#define OFF_M9  8126464u
#define OFF_M10 8192000u
#define MEM_TOTAL 8257536u

__device__ float g_mem[MEM_TOTAL];
__device__ float g_A[2097152];
__device__ float g_B[2097152];
__device__ float g_C[2097152];
__device__ float g_D[2097152];   // precomputed conv(x, w_pre0)

__global__ void zero_kernel(float* __restrict__ p, int n) {
    int i = blockIdx.x * blockDim.x + threadIdx.x;
    if (i < n) p[i] = 0.0f;
}

// elementwise LIF for layer 0, float4-vectorized (delta precomputed)
__global__ __launch_bounds__(256)
void lif0_kernel(const float4* __restrict__ delta, float4* __restrict__ mem,
                 const float4* __restrict__ mask, float4* __restrict__ out,
                 const float* __restrict__ thr_a, const float* __restrict__ leak_a) {
    int i = blockIdx.x * blockDim.x + threadIdx.x;
    float thr = __ldg(thr_a), leak = __ldg(leak_a);
    float4 d = __ldg(delta + i);
    float4 mm = mem[i];
    float4 mk = __ldg(mask + i);
    float4 o, nm;
    { float m = fmaf(leak, mm.x, d.x); float s = (m / thr > 1.0f) ? 1.0f : 0.0f;
      nm.x = m - thr * s; o.x = s * mk.x; }
    { float m = fmaf(leak, mm.y, d.y); float s = (m / thr > 1.0f) ? 1.0f : 0.0f;
      nm.y = m - thr * s; o.y = s * mk.y; }
    { float m = fmaf(leak, mm.z, d.z); float s = (m / thr > 1.0f) ? 1.0f : 0.0f;
      nm.z = m - thr * s; o.z = s * mk.z; }
    { float m = fmaf(leak, mm.w, d.w); float s = (m / thr > 1.0f) ? 1.0f : 0.0f;
      nm.w = m - thr * s; o.w = s * mk.w; }
    mem[i] = nm;
    out[i] = o;
}

// ---------------------------------------------------------------------------
// Fused 3x3 conv (pad=1) + (residual | fused 1x1-s2 shortcut) + LIF + mask
// (+ optional fused 2x2 avgpool). Double-buffered cp.async chunk staging.
// mem == nullptr  =>  raw conv output (no LIF), used for hoisted layer 0.
// ---------------------------------------------------------------------------
template<int H, int CI, int CO, int STRIDE, int CIC, int TH, int TW,
         int CO_T, int B_T, int NT, int SC_CI, int POOL>
__global__ __launch_bounds__(NT)
void conv_fused(const float* __restrict__ in, const float* __restrict__ wgt,
                const float* __restrict__ res, const float* __restrict__ mask,
                const float* __restrict__ sc_in, const float* __restrict__ sc_w,
                float* __restrict__ mem, float* __restrict__ out,
                const float* __restrict__ thr_a, const float* __restrict__ leak_a,
                int lidx) {
    constexpr int HO = H / STRIDE;
    constexpr int WO = HO;
    constexpr int TILESH = HO / TH;
    constexpr int TILESW = WO / TW;
    constexpr int TILES = TILESH * TILESW;
    static_assert(TILES * CO_T * B_T == NT, "thread count mismatch");
    static_assert((TW * STRIDE) % 4 == 0 || TILESW == 1, "LDS.128 alignment");
    constexpr int RH = (TH - 1) * STRIDE + 3;
    constexpr int RW = (TW - 1) * STRIDE + 3;
    constexpr int NV4 = (RW + 3) / 4;
    constexpr int SWMIN = (H + 2 > NV4 * 4) ? (H + 2) : (NV4 * 4);
    constexpr int SW = ((SWMIN + 3) / 4) * 4;   // smem row stride (interior col 1)
    constexpr int HI2 = H + 2;
    constexpr int IN_CH = HI2 * SW;
    constexpr int IN_IMG = CIC * IN_CH;
    constexpr int IN_TOT = B_T * IN_IMG;
    constexpr int W_CO = CIC * 9;
    constexpr int W_STRIDE = W_CO + 1;          // ODD stride -> conflict-free
    constexpr int W_TOT = CO_T * W_STRIDE;
    constexpr int CHUNKS = CI / CIC;
    constexpr int THW = TH * TW;

    __shared__ alignas(16) float s_in[2][IN_TOT];
    __shared__ alignas(16) float s_w[2][W_TOT];

    const int tid = threadIdx.x;
    const int tile = tid % TILES;
    const int co_l = (tid / TILES) % CO_T;
    const int b_l  = tid / (TILES * CO_T);
    const int co_g = blockIdx.x % (CO / CO_T);
    const int b_g  = blockIdx.x / (CO / CO_T);
    const int b  = b_g * B_T + b_l;
    const int co = co_g * CO_T + co_l;
    const int oh0 = (tile / TILESW) * TH;
    const int ow0 = (tile % TILESW) * TW;

    // zero both input buffers once: halo / padding stays zero for all chunks
    {
        const float4 z4 = make_float4(0.f, 0.f, 0.f, 0.f);
        for (int i = tid * 4; i < IN_TOT; i += NT * 4) {
            *reinterpret_cast<float4*>(&s_in[0][i]) = z4;
            *reinterpret_cast<float4*>(&s_in[1][i]) = z4;
        }
    }
    __syncthreads();

    auto stage = [&](int buf, int cc) {
        constexpr int NE = B_T * CIC * H * H;
        for (int e = tid; e < NE; e += NT) {
            const int wq = e % H;
            int r = e / H;
            const int h = r % H; r /= H;
            const int ci = r % CIC;
            const int bl = r / CIC;
            const float* src = in + (((size_t)(b_g * B_T + bl) * CI + cc * CIC + ci) * H + h) * H + wq;
            __pipeline_memcpy_async(&s_in[buf][bl * IN_IMG + ci * IN_CH + (h + 1) * SW + 1 + wq],
                                    src, 4);
        }
        for (int e = tid; e < CO_T * W_CO; e += NT) {
            const int rem = e % W_CO;
            const int col = e / W_CO;
            const float* src = wgt + ((size_t)(co_g * CO_T + col) * CI + cc * CIC) * 9 + rem;
            __pipeline_memcpy_async(&s_w[buf][col * W_STRIDE + rem], src, 4);
        }
    };

    float acc[THW];
#pragma unroll
    for (int i = 0; i < THW; ++i) acc[i] = 0.0f;

    stage(0, 0);
    __pipeline_commit();

    for (int cc = 0; cc < CHUNKS; ++cc) {
        const int cur = cc & 1;
        if (cc + 1 < CHUNKS) {
            stage(cur ^ 1, cc + 1);
            __pipeline_commit();
            __pipeline_wait_prior(1);
        } else {
            __pipeline_wait_prior(0);
        }
        __syncthreads();

        const float* sin_b = &s_in[cur][b_l * IN_IMG + (oh0 * STRIDE) * SW + ow0 * STRIDE];
        const float* sw_c  = &s_w[cur][co_l * W_STRIDE];
        for (int ci = 0; ci < CIC; ++ci) {
            float w9[9];
#pragma unroll
            for (int k = 0; k < 9; ++k) w9[k] = sw_c[ci * 9 + k];
            const float* sp = sin_b + ci * IN_CH;
#pragma unroll
            for (int r = 0; r < RH; ++r) {
                float v[NV4 * 4];
#pragma unroll
                for (int q = 0; q < NV4; ++q)
                    *reinterpret_cast<float4*>(v + 4 * q) =
                        *reinterpret_cast<const float4*>(sp + r * SW + 4 * q);
#pragma unroll
                for (int kh = 0; kh < 3; ++kh) {
                    if (r - kh >= 0 && (r - kh) % STRIDE == 0 && (r - kh) / STRIDE < TH) {
                        const int ii = (r - kh) / STRIDE;
#pragma unroll
                        for (int kw = 0; kw < 3; ++kw)
#pragma unroll
                            for (int j = 0; j < TW; ++j)
                                acc[ii * TW + j] = fmaf(w9[kh * 3 + kw],
                                                        v[j * STRIDE + kw],
                                                        acc[ii * TW + j]);
                    }
                }
            }
        }
        __syncthreads();
    }

    // fused 1x1-s2 shortcut conv
    float rsum[THW];
    if (SC_CI > 0) {
#pragma unroll
        for (int i = 0; i < THW; ++i) rsum[i] = 0.0f;
        const float* wp = sc_w + (size_t)co * SC_CI;
        for (int ci = 0; ci < SC_CI; ++ci) {
            float wv = __ldg(wp + ci);
            const float* ip = sc_in + ((size_t)b * SC_CI + ci) * (4 * HO * WO);
#pragma unroll
            for (int i = 0; i < TH; ++i)
#pragma unroll
                for (int j = 0; j < TW; ++j)
                    rsum[i * TW + j] = fmaf(wv,
                        __ldg(ip + (2 * (oh0 + i)) * (2 * WO) + 2 * (ow0 + j)),
                        rsum[i * TW + j]);
        }
    }

    const float thr  = __ldg(thr_a + lidx);
    const float leak = __ldg(leak_a + lidx);

    float s_tile[THW];
#pragma unroll
    for (int i = 0; i < TH; ++i) {
#pragma unroll
        for (int j = 0; j < TW; ++j) {
            size_t oi = (((size_t)b * CO + co) * HO + oh0 + i) * WO + ow0 + j;
            float d = acc[i * TW + j];
            if (SC_CI > 0) d += rsum[i * TW + j];
            else if (res) d += __ldg(res + oi);
            if (mem == nullptr) { out[oi] = d; continue; }
            float m = fmaf(leak, mem[oi], d);
            float mth = m / thr - 1.0f;
            float s = (mth > 0.0f) ? 1.0f : 0.0f;
            mem[oi] = m - thr * s;
            if (POOL) s_tile[i * TW + j] = s;
            else out[oi] = mask ? s * __ldg(mask + oi) : s;
        }
    }
    if (POOL && mem != nullptr) {
        constexpr int HOP = HO / 2, WOP = WO / 2;
#pragma unroll
        for (int i2 = 0; i2 < TH / 2; ++i2)
#pragma unroll
            for (int j2 = 0; j2 < TW / 2; ++j2) {
                float sum = s_tile[(2 * i2) * TW + 2 * j2] +
                            s_tile[(2 * i2) * TW + 2 * j2 + 1] +
                            s_tile[(2 * i2 + 1) * TW + 2 * j2] +
                            s_tile[(2 * i2 + 1) * TW + 2 * j2 + 1];
                out[(((size_t)b * CO + co) * HOP + (oh0 >> 1) + i2) * WOP +
                    (ow0 >> 1) + j2] = 0.25f * sum;
            }
    }
}

// FC accumulate: out[b,j] += sum_k in[b,k] * wfc[j,k].  One warp per output.
__global__ __launch_bounds__(256)
void fc_acc(const float* __restrict__ in, const float* __restrict__ wfc,
            float* __restrict__ out) {
    int gw = (blockIdx.x * blockDim.x + threadIdx.x) >> 5;
    int lane = threadIdx.x & 31;
    if (gw >= B * 10) return;
    int b = gw / 10, j = gw % 10;
    const float* x = in + (size_t)b * 2048;
    const float* w = wfc + (size_t)j * 2048;
    float s = 0.f;
    for (int k = lane; k < 2048; k += 32) s = fmaf(x[k], w[k], s);
#pragma unroll
    for (int o = 16; o; o >>= 1) s += __shfl_down_sync(0xffffffffu, s, o);
    if (lane == 0) out[b * 10 + j] += s;
}

// -------------------------- host-side orchestration ------------------------

extern "C" void kernel_launch(void* const* d_in, const int* in_sizes, int n_in,
                              void* d_out, int out_size) {
    const float* x      = (const float*)d_in[0];
    const float* w_pre0 = (const float*)d_in[1];
    const float* w_pre1 = (const float*)d_in[2];
    const float* w_pre2 = (const float*)d_in[3];
    const float* w1a    = (const float*)d_in[4];
    const float* w1b    = (const float*)d_in[5];
    const float* w2a    = (const float*)d_in[6];
    const float* w2b    = (const float*)d_in[7];
    const float* w2i    = (const float*)d_in[8];
    const float* w3a    = (const float*)d_in[9];
    const float* w3b    = (const float*)d_in[10];
    const float* w3i    = (const float*)d_in[11];
    const float* w4a    = (const float*)d_in[12];
    const float* w4b    = (const float*)d_in[13];
    const float* w4i    = (const float*)d_in[14];
    const float* w_fc   = (const float*)d_in[15];
    const float* thr    = (const float*)d_in[16];
    const float* leak   = (const float*)d_in[17];
    const float* mask2  = (const float*)d_in[18];
    const float* mask5  = (const float*)d_in[19];
    const float* mask9  = (const float*)d_in[20];
    const float* mask11 = (const float*)d_in[21];
    const float* mask13 = (const float*)d_in[22];
    const float* mask15 = (const float*)d_in[23];

    float *pm, *pA, *pB, *pC, *pD;
    cudaGetSymbolAddress((void**)&pm, g_mem);
    cudaGetSymbolAddress((void**)&pA, g_A);
    cudaGetSymbolAddress((void**)&pB, g_B);
    cudaGetSymbolAddress((void**)&pC, g_C);
    cudaGetSymbolAddress((void**)&pD, g_D);

    float* m0  = pm + OFF_M0;
    float* m1  = pm + OFF_M1;
    float* m2  = pm + OFF_M2;
    float* m3  = pm + OFF_M3;
    float* m4  = pm + OFF_M4;
    float* m5  = pm + OFF_M5;
    float* m6  = pm + OFF_M6;
    float* m7  = pm + OFF_M7;
    float* m8  = pm + OFF_M8;
    float* m9  = pm + OFF_M9;
    float* m10 = pm + OFF_M10;

    zero_kernel<<<(MEM_TOTAL + 255) / 256, 256>>>(pm, (int)MEM_TOTAL);
    zero_kernel<<<2, 256>>>((float*)d_out, out_size);

    // hoisted: delta0 = conv(x, w_pre0), constant across timesteps
    conv_fused<32, 3, 64, 1, 3, 4, 4, 4, 1, 256, 0, 0><<<512, 256>>>(
        x, w_pre0, nullptr, nullptr, nullptr, nullptr, nullptr, pD, thr, leak, 0);

    for (int t = 0; t < TSTEPS; ++t) {
        // layer 0: elementwise LIF on precomputed delta (float4)
        lif0_kernel<<<2048, 256>>>((const float4*)pD, (float4*)m0,
                                   (const float4*)mask2, (float4*)pA, thr + 0, leak + 0);

        // pre-process convs (32x32, 64ch); pre2 fuses the 2x2 avgpool
        conv_fused<32, 64, 64, 1, 4, 4, 4, 4, 1, 256, 0, 0><<<512, 256>>>(
            pA, w_pre1, nullptr, mask5, nullptr, nullptr, m1, pB, thr, leak, 1);
        conv_fused<32, 64, 64, 1, 4, 4, 4, 4, 1, 256, 0, 1><<<512, 256>>>(
            pB, w_pre2, nullptr, nullptr, nullptr, nullptr, m2, pC, thr, leak, 2);

        // layer1 (identity shortcut), 16x16x64
        conv_fused<16, 64, 64, 1, 8, 4, 4, 16, 1, 256, 0, 0><<<128, 256>>>(
            pC, w1a, nullptr, mask9, nullptr, nullptr, m3, pA, thr, leak, 3);
        conv_fused<16, 64, 64, 1, 8, 4, 4, 16, 1, 256, 0, 0><<<128, 256>>>(
            pA, w1b, pC, nullptr, nullptr, nullptr, m4, pB, thr, leak, 4);

        // layer2: 16x16x64 -> 8x8x128 (fused 1x1-s2 shortcut in conv-b)
        conv_fused<16, 64, 128, 2, 4, 2, 4, 16, 2, 256, 0, 0><<<128, 256>>>(
            pB, w2a, nullptr, mask11, nullptr, nullptr, m5, pC, thr, leak, 5);
        conv_fused<8, 128, 128, 1, 8, 4, 4, 16, 2, 128, 64, 0><<<128, 128>>>(
            pC, w2b, nullptr, nullptr, pB, w2i, m6, pA, thr, leak, 6);

        // layer3: 8x8x128 -> 4x4x256
        conv_fused<8, 128, 256, 2, 8, 2, 2, 16, 2, 128, 0, 0><<<256, 128>>>(
            pA, w3a, nullptr, mask13, nullptr, nullptr, m7, pB, thr, leak, 7);
        conv_fused<4, 256, 256, 1, 8, 2, 4, 32, 2, 128, 128, 0><<<128, 128>>>(
            pB, w3b, nullptr, nullptr, pA, w3i, m8, pC, thr, leak, 8);

        // layer4: 4x4x256 -> 2x2x512
        conv_fused<4, 256, 512, 2, 8, 2, 2, 32, 4, 128, 0, 0><<<128, 128>>>(
            pC, w4a, nullptr, mask15, nullptr, nullptr, m9, pB, thr, leak, 9);
        conv_fused<2, 512, 512, 1, 16, 2, 2, 32, 4, 128, 256, 0><<<128, 128>>>(
            pB, w4b, nullptr, nullptr, pC, w4i, m10, pA, thr, leak, 10);

        // classifier accumulation
        fc_acc<<<40, 256>>>(pA, w_fc, (float*)d_out);
    }
}

// round 14
// speedup vs baseline: 1.3858x; 1.0550x over previous
#include <cuda_runtime.h>
#include <cuda_pipeline.h>

// ---------------------------------------------------------------------------
// SNN ResNet forward, 8 timesteps, B=32. fp32 smem-tiled convs with cp.async
// double buffering, odd-stride weight smem (conflict-free), CO_PT output
// channels per thread (input-load reuse). Fused LIF / masks / residuals /
// 1x1-s2 shortcuts / avgpool; layer-0 conv hoisted.
// ---------------------------------------------------------------------------

#define B 32
#define TSTEPS 8

#define OFF_M0  0u
#define OFF_M1  2097152u
#define OFF_M2  4194304u
#define OFF_M3  6291456u
#define OFF_M4  6815744u
#define OFF_M5  7340032u
#define OFF_M6  7602176u
#define OFF_M7  7864320u
#define OFF_M8  7995392u
#define OFF_M9  8126464u
#define OFF_M10 8192000u
#define MEM_TOTAL 8257536u

__device__ float g_mem[MEM_TOTAL];
__device__ float g_A[2097152];
__device__ float g_B[2097152];
__device__ float g_C[2097152];
__device__ float g_D[2097152];   // precomputed conv(x, w_pre0)

__global__ void zero_kernel(float* __restrict__ p, int n) {
    int i = blockIdx.x * blockDim.x + threadIdx.x;
    if (i < n) p[i] = 0.0f;
}

// elementwise LIF for layer 0, float4-vectorized (delta precomputed)
__global__ __launch_bounds__(256)
void lif0_kernel(const float4* __restrict__ delta, float4* __restrict__ mem,
                 const float4* __restrict__ mask, float4* __restrict__ out,
                 const float* __restrict__ thr_a, const float* __restrict__ leak_a) {
    int i = blockIdx.x * blockDim.x + threadIdx.x;
    float thr = __ldg(thr_a), leak = __ldg(leak_a);
    float4 d = __ldg(delta + i);
    float4 mm = mem[i];
    float4 mk = __ldg(mask + i);
    float4 o, nm;
    { float m = fmaf(leak, mm.x, d.x); float s = (m / thr > 1.0f) ? 1.0f : 0.0f;
      nm.x = m - thr * s; o.x = s * mk.x; }
    { float m = fmaf(leak, mm.y, d.y); float s = (m / thr > 1.0f) ? 1.0f : 0.0f;
      nm.y = m - thr * s; o.y = s * mk.y; }
    { float m = fmaf(leak, mm.z, d.z); float s = (m / thr > 1.0f) ? 1.0f : 0.0f;
      nm.z = m - thr * s; o.z = s * mk.z; }
    { float m = fmaf(leak, mm.w, d.w); float s = (m / thr > 1.0f) ? 1.0f : 0.0f;
      nm.w = m - thr * s; o.w = s * mk.w; }
    mem[i] = nm;
    out[i] = o;
}

// ---------------------------------------------------------------------------
// Fused 3x3 conv (pad=1) + (residual | fused 1x1-s2 shortcut) + LIF + mask
// (+ optional fused 2x2 avgpool). Double-buffered cp.async chunk staging.
// Each thread computes CO_PT consecutive output channels (input-load reuse).
// mem == nullptr  =>  raw conv output (no LIF), used for hoisted layer 0.
// ---------------------------------------------------------------------------
template<int H, int CI, int CO, int STRIDE, int CIC, int TH, int TW,
         int CO_T, int B_T, int NT, int SC_CI, int POOL, int CO_PT>
__global__ __launch_bounds__(NT)
void conv_fused(const float* __restrict__ in, const float* __restrict__ wgt,
                const float* __restrict__ res, const float* __restrict__ mask,
                const float* __restrict__ sc_in, const float* __restrict__ sc_w,
                float* __restrict__ mem, float* __restrict__ out,
                const float* __restrict__ thr_a, const float* __restrict__ leak_a,
                int lidx) {
    constexpr int HO = H / STRIDE;
    constexpr int WO = HO;
    constexpr int TILESH = HO / TH;
    constexpr int TILESW = WO / TW;
    constexpr int TILES = TILESH * TILESW;
    constexpr int CO_G = CO_T / CO_PT;
    static_assert(TILES * CO_G * B_T == NT, "thread count mismatch");
    static_assert((TW * STRIDE) % 4 == 0 || TILESW == 1, "LDS.128 alignment");
    constexpr int RH = (TH - 1) * STRIDE + 3;
    constexpr int RW = (TW - 1) * STRIDE + 3;
    constexpr int NV4 = (RW + 3) / 4;
    constexpr int SWMIN = (H + 2 > NV4 * 4) ? (H + 2) : (NV4 * 4);
    constexpr int SW = ((SWMIN + 3) / 4) * 4;   // smem row stride (interior col 1)
    constexpr int HI2 = H + 2;
    constexpr int IN_CH = HI2 * SW;
    constexpr int IN_IMG = CIC * IN_CH;
    constexpr int IN_TOT = B_T * IN_IMG;
    constexpr int W_CO = CIC * 9;
    constexpr int W_STRIDE = W_CO + 1;          // ODD stride -> conflict-free
    constexpr int W_TOT = CO_T * W_STRIDE;
    constexpr int CHUNKS = CI / CIC;
    constexpr int THW = TH * TW;

    __shared__ alignas(16) float s_in[2][IN_TOT];
    __shared__ alignas(16) float s_w[2][W_TOT];

    const int tid = threadIdx.x;
    const int tile = tid % TILES;
    const int cs   = (tid / TILES) % CO_G;
    const int b_l  = tid / (TILES * CO_G);
    const int co_g = blockIdx.x % (CO / CO_T);
    const int b_g  = blockIdx.x / (CO / CO_T);
    const int b  = b_g * B_T + b_l;
    const int co = co_g * CO_T + cs * CO_PT;
    const int oh0 = (tile / TILESW) * TH;
    const int ow0 = (tile % TILESW) * TW;

    // zero both input buffers once: halo / padding stays zero for all chunks
    {
        const float4 z4 = make_float4(0.f, 0.f, 0.f, 0.f);
        for (int i = tid * 4; i < IN_TOT; i += NT * 4) {
            *reinterpret_cast<float4*>(&s_in[0][i]) = z4;
            *reinterpret_cast<float4*>(&s_in[1][i]) = z4;
        }
    }
    __syncthreads();

    auto stage = [&](int buf, int cc) {
        constexpr int NE = B_T * CIC * H * H;
        for (int e = tid; e < NE; e += NT) {
            const int wq = e % H;
            int r = e / H;
            const int h = r % H; r /= H;
            const int ci = r % CIC;
            const int bl = r / CIC;
            const float* src = in + (((size_t)(b_g * B_T + bl) * CI + cc * CIC + ci) * H + h) * H + wq;
            __pipeline_memcpy_async(&s_in[buf][bl * IN_IMG + ci * IN_CH + (h + 1) * SW + 1 + wq],
                                    src, 4);
        }
        for (int e = tid; e < CO_T * W_CO; e += NT) {
            const int rem = e % W_CO;
            const int col = e / W_CO;
            const float* src = wgt + ((size_t)(co_g * CO_T + col) * CI + cc * CIC) * 9 + rem;
            __pipeline_memcpy_async(&s_w[buf][col * W_STRIDE + rem], src, 4);
        }
    };

    float acc[CO_PT][THW];
#pragma unroll
    for (int p = 0; p < CO_PT; ++p)
#pragma unroll
        for (int i = 0; i < THW; ++i) acc[p][i] = 0.0f;

    stage(0, 0);
    __pipeline_commit();

    for (int cc = 0; cc < CHUNKS; ++cc) {
        const int cur = cc & 1;
        if (cc + 1 < CHUNKS) {
            stage(cur ^ 1, cc + 1);
            __pipeline_commit();
            __pipeline_wait_prior(1);
        } else {
            __pipeline_wait_prior(0);
        }
        __syncthreads();

        const float* sin_b = &s_in[cur][b_l * IN_IMG + (oh0 * STRIDE) * SW + ow0 * STRIDE];
        const float* sw_c  = &s_w[cur][(cs * CO_PT) * W_STRIDE];
        for (int ci = 0; ci < CIC; ++ci) {
            float w9[CO_PT][9];
#pragma unroll
            for (int p = 0; p < CO_PT; ++p)
#pragma unroll
                for (int k = 0; k < 9; ++k) w9[p][k] = sw_c[p * W_STRIDE + ci * 9 + k];
            const float* sp = sin_b + ci * IN_CH;
#pragma unroll
            for (int r = 0; r < RH; ++r) {
                float v[NV4 * 4];
#pragma unroll
                for (int q = 0; q < NV4; ++q)
                    *reinterpret_cast<float4*>(v + 4 * q) =
                        *reinterpret_cast<const float4*>(sp + r * SW + 4 * q);
#pragma unroll
                for (int kh = 0; kh < 3; ++kh) {
                    if (r - kh >= 0 && (r - kh) % STRIDE == 0 && (r - kh) / STRIDE < TH) {
                        const int ii = (r - kh) / STRIDE;
#pragma unroll
                        for (int kw = 0; kw < 3; ++kw)
#pragma unroll
                            for (int j = 0; j < TW; ++j)
#pragma unroll
                                for (int p = 0; p < CO_PT; ++p)
                                    acc[p][ii * TW + j] = fmaf(w9[p][kh * 3 + kw],
                                                               v[j * STRIDE + kw],
                                                               acc[p][ii * TW + j]);
                    }
                }
            }
        }
        __syncthreads();
    }

    // fused 1x1-s2 shortcut conv (input loads shared across CO_PT)
    float rsum[CO_PT][THW];
    if (SC_CI > 0) {
#pragma unroll
        for (int p = 0; p < CO_PT; ++p)
#pragma unroll
            for (int i = 0; i < THW; ++i) rsum[p][i] = 0.0f;
        for (int ci = 0; ci < SC_CI; ++ci) {
            float wv[CO_PT];
#pragma unroll
            for (int p = 0; p < CO_PT; ++p)
                wv[p] = __ldg(sc_w + (size_t)(co + p) * SC_CI + ci);
            const float* ip = sc_in + ((size_t)b * SC_CI + ci) * (4 * HO * WO);
#pragma unroll
            for (int i = 0; i < TH; ++i)
#pragma unroll
                for (int j = 0; j < TW; ++j) {
                    float iv = __ldg(ip + (2 * (oh0 + i)) * (2 * WO) + 2 * (ow0 + j));
#pragma unroll
                    for (int p = 0; p < CO_PT; ++p)
                        rsum[p][i * TW + j] = fmaf(wv[p], iv, rsum[p][i * TW + j]);
                }
        }
    }

    const float thr  = __ldg(thr_a + lidx);
    const float leak = __ldg(leak_a + lidx);

#pragma unroll
    for (int p = 0; p < CO_PT; ++p) {
        const int co_p = co + p;
        float s_tile[THW];
#pragma unroll
        for (int i = 0; i < TH; ++i) {
#pragma unroll
            for (int j = 0; j < TW; ++j) {
                size_t oi = (((size_t)b * CO + co_p) * HO + oh0 + i) * WO + ow0 + j;
                float d = acc[p][i * TW + j];
                if (SC_CI > 0) d += rsum[p][i * TW + j];
                else if (res) d += __ldg(res + oi);
                if (mem == nullptr) { out[oi] = d; continue; }
                float m = fmaf(leak, mem[oi], d);
                float mth = m / thr - 1.0f;
                float s = (mth > 0.0f) ? 1.0f : 0.0f;
                mem[oi] = m - thr * s;
                if (POOL) s_tile[i * TW + j] = s;
                else out[oi] = mask ? s * __ldg(mask + oi) : s;
            }
        }
        if (POOL && mem != nullptr) {
            constexpr int HOP = HO / 2, WOP = WO / 2;
#pragma unroll
            for (int i2 = 0; i2 < TH / 2; ++i2)
#pragma unroll
                for (int j2 = 0; j2 < TW / 2; ++j2) {
                    float sum = s_tile[(2 * i2) * TW + 2 * j2] +
                                s_tile[(2 * i2) * TW + 2 * j2 + 1] +
                                s_tile[(2 * i2 + 1) * TW + 2 * j2] +
                                s_tile[(2 * i2 + 1) * TW + 2 * j2 + 1];
                    out[(((size_t)b * CO + co_p) * HOP + (oh0 >> 1) + i2) * WOP +
                        (ow0 >> 1) + j2] = 0.25f * sum;
                }
        }
    }
}

// FC accumulate: out[b,j] += sum_k in[b,k] * wfc[j,k].  One warp per output.
__global__ __launch_bounds__(256)
void fc_acc(const float* __restrict__ in, const float* __restrict__ wfc,
            float* __restrict__ out) {
    int gw = (blockIdx.x * blockDim.x + threadIdx.x) >> 5;
    int lane = threadIdx.x & 31;
    if (gw >= B * 10) return;
    int b = gw / 10, j = gw % 10;
    const float* x = in + (size_t)b * 2048;
    const float* w = wfc + (size_t)j * 2048;
    float s = 0.f;
    for (int k = lane; k < 2048; k += 32) s = fmaf(x[k], w[k], s);
#pragma unroll
    for (int o = 16; o; o >>= 1) s += __shfl_down_sync(0xffffffffu, s, o);
    if (lane == 0) out[b * 10 + j] += s;
}

// -------------------------- host-side orchestration ------------------------

extern "C" void kernel_launch(void* const* d_in, const int* in_sizes, int n_in,
                              void* d_out, int out_size) {
    const float* x      = (const float*)d_in[0];
    const float* w_pre0 = (const float*)d_in[1];
    const float* w_pre1 = (const float*)d_in[2];
    const float* w_pre2 = (const float*)d_in[3];
    const float* w1a    = (const float*)d_in[4];
    const float* w1b    = (const float*)d_in[5];
    const float* w2a    = (const float*)d_in[6];
    const float* w2b    = (const float*)d_in[7];
    const float* w2i    = (const float*)d_in[8];
    const float* w3a    = (const float*)d_in[9];
    const float* w3b    = (const float*)d_in[10];
    const float* w3i    = (const float*)d_in[11];
    const float* w4a    = (const float*)d_in[12];
    const float* w4b    = (const float*)d_in[13];
    const float* w4i    = (const float*)d_in[14];
    const float* w_fc   = (const float*)d_in[15];
    const float* thr    = (const float*)d_in[16];
    const float* leak   = (const float*)d_in[17];
    const float* mask2  = (const float*)d_in[18];
    const float* mask5  = (const float*)d_in[19];
    const float* mask9  = (const float*)d_in[20];
    const float* mask11 = (const float*)d_in[21];
    const float* mask13 = (const float*)d_in[22];
    const float* mask15 = (const float*)d_in[23];

    float *pm, *pA, *pB, *pC, *pD;
    cudaGetSymbolAddress((void**)&pm, g_mem);
    cudaGetSymbolAddress((void**)&pA, g_A);
    cudaGetSymbolAddress((void**)&pB, g_B);
    cudaGetSymbolAddress((void**)&pC, g_C);
    cudaGetSymbolAddress((void**)&pD, g_D);

    float* m0  = pm + OFF_M0;
    float* m1  = pm + OFF_M1;
    float* m2  = pm + OFF_M2;
    float* m3  = pm + OFF_M3;
    float* m4  = pm + OFF_M4;
    float* m5  = pm + OFF_M5;
    float* m6  = pm + OFF_M6;
    float* m7  = pm + OFF_M7;
    float* m8  = pm + OFF_M8;
    float* m9  = pm + OFF_M9;
    float* m10 = pm + OFF_M10;

    zero_kernel<<<(MEM_TOTAL + 255) / 256, 256>>>(pm, (int)MEM_TOTAL);
    zero_kernel<<<2, 256>>>((float*)d_out, out_size);

    // hoisted: delta0 = conv(x, w_pre0), constant across timesteps
    conv_fused<32, 3, 64, 1, 3, 4, 4, 4, 1, 256, 0, 0, 1><<<512, 256>>>(
        x, w_pre0, nullptr, nullptr, nullptr, nullptr, nullptr, pD, thr, leak, 0);

    for (int t = 0; t < TSTEPS; ++t) {
        // layer 0: elementwise LIF on precomputed delta (float4)
        lif0_kernel<<<2048, 256>>>((const float4*)pD, (float4*)m0,
                                   (const float4*)mask2, (float4*)pA, thr + 0, leak + 0);

        // pre-process convs (32x32, 64ch), CO_PT=2; pre2 fuses the avgpool
        conv_fused<32, 64, 64, 1, 4, 4, 4, 8, 1, 256, 0, 0, 2><<<256, 256>>>(
            pA, w_pre1, nullptr, mask5, nullptr, nullptr, m1, pB, thr, leak, 1);
        conv_fused<32, 64, 64, 1, 4, 4, 4, 8, 1, 256, 0, 1, 2><<<256, 256>>>(
            pB, w_pre2, nullptr, nullptr, nullptr, nullptr, m2, pC, thr, leak, 2);

        // layer1 (identity shortcut), 16x16x64
        conv_fused<16, 64, 64, 1, 8, 4, 4, 16, 1, 256, 0, 0, 1><<<128, 256>>>(
            pC, w1a, nullptr, mask9, nullptr, nullptr, m3, pA, thr, leak, 3);
        conv_fused<16, 64, 64, 1, 8, 4, 4, 16, 1, 256, 0, 0, 1><<<128, 256>>>(
            pA, w1b, pC, nullptr, nullptr, nullptr, m4, pB, thr, leak, 4);

        // layer2: 16x16x64 -> 8x8x128 (fused 1x1-s2 shortcut in conv-b)
        conv_fused<16, 64, 128, 2, 4, 2, 4, 16, 2, 256, 0, 0, 1><<<128, 256>>>(
            pB, w2a, nullptr, mask11, nullptr, nullptr, m5, pC, thr, leak, 5);
        conv_fused<8, 128, 128, 1, 8, 4, 4, 16, 2, 128, 64, 0, 1><<<128, 128>>>(
            pC, w2b, nullptr, nullptr, pB, w2i, m6, pA, thr, leak, 6);

        // layer3: 8x8x128 -> 4x4x256
        conv_fused<8, 128, 256, 2, 8, 2, 2, 16, 2, 128, 0, 0, 1><<<256, 128>>>(
            pA, w3a, nullptr, mask13, nullptr, nullptr, m7, pB, thr, leak, 7);
        conv_fused<4, 256, 256, 1, 8, 2, 4, 32, 2, 128, 128, 0, 1><<<128, 128>>>(
            pB, w3b, nullptr, nullptr, pA, w3i, m8, pC, thr, leak, 8);

        // layer4: 4x4x256 -> 2x2x512
        conv_fused<4, 256, 512, 2, 8, 2, 2, 32, 4, 128, 0, 0, 1><<<128, 128>>>(
            pC, w4a, nullptr, mask15, nullptr, nullptr, m9, pB, thr, leak, 9);
        conv_fused<2, 512, 512, 1, 16, 2, 2, 32, 4, 128, 256, 0, 1><<<128, 128>>>(
            pB, w4b, nullptr, nullptr, pC, w4i, m10, pA, thr, leak, 10);

        // classifier accumulation
        fc_acc<<<40, 256>>>(pA, w_fc, (float*)d_out);
    }
}